// round 2
// baseline (speedup 1.0000x reference)
#include <cuda_runtime.h>
#include <math.h>

#define NN 4096
#define MM 8192
#define GG 8
#define HH 128
#define NDD 16
#define EE 131072

// ---------------- device scratch (no allocations allowed) ----------------
// All referenced ONLY from device code (host-side use of __device__ symbols is UB).
__device__ float g_buf[3][NN*HH];   // 0: node_emb / h2, 1: xw scratch, 2: h1
__device__ int   g_cnt[NN];
__device__ int   g_cur[NN];
__device__ int   g_rowptr[NN+1];
__device__ int   g_csr[EE];
__device__ float g_dinv[NN];
__device__ float g_condsum[GG*HH];
__device__ float g_condcnt[GG];
__device__ float g_gh[GG*HH];       // time_h + cond_h per graph
__device__ float g_sl[NN];
__device__ float g_sr[NN];
__device__ int   g_flags[2];        // 1 => mask input is int32, 0 => byte bool

// ---------------- init ----------------
__global__ void k_zero() {
    int i = blockIdx.x * blockDim.x + threadIdx.x;
    int stride = gridDim.x * blockDim.x;
    for (int j = i; j < NN; j += stride) { g_cnt[j] = 0; g_cur[j] = 0; }
    for (int j = i; j < GG*HH; j += stride) g_condsum[j] = 0.f;
    for (int j = i; j < GG; j += stride) g_condcnt[j] = 0.f;
    if (i < 2) g_flags[i] = 1;
}

// detect int32 vs byte bool layout: int32 0/1 arrays have zero bytes at idx%4!=0
__global__ void k_detect(const unsigned char* p0, const unsigned char* p1, int m) {
    int i = blockIdx.x * blockDim.x + threadIdx.x;
    if (i < m && (i & 3) != 0) {
        if (p0[i]) atomicExch(&g_flags[0], 0);
        if (p1[i]) atomicExch(&g_flags[1], 0);
    }
}

// ---------------- cond pooling (exploits sorted obj_batch) ----------------
__global__ void k_cond_pool(const float* __restrict__ obj_x, const float* __restrict__ obj_pos,
                            const int* __restrict__ nuc, const void* central, const void* backbone,
                            const int* __restrict__ obatch,
                            const float* __restrict__ Wn, const float* __restrict__ bn) {
    const int c = threadIdx.x;          // 0..127
    const int m0 = blockIdx.x * 32;
    const int fC = g_flags[0], fB = g_flags[1];
    float acc = 0.f; float cntloc = 0.f; int cur_g = -1;
    for (int mm = 0; mm < 32; mm++) {
        int m = m0 + mm;
        if (m >= MM) break;
        int nv = nuc[m];
        bool cen = fC ? (((const int*)central)[m] != 0) : (((const unsigned char*)central)[m] != 0);
        bool bb  = fB ? (((const int*)backbone)[m] != 0) : (((const unsigned char*)backbone)[m] != 0);
        bool base = !bb;
        bool cond = (nv == 0) || (cen && base) || ((nv == 2) && base);
        if (!cond) continue;
        int g = obatch[m];
        float e = bn[c];
        #pragma unroll
        for (int k = 0; k < 13; k++) e += obj_x[m*13 + k] * Wn[k*HH + c];
        #pragma unroll
        for (int k = 0; k < 3; k++)  e += obj_pos[m*3 + k] * Wn[(13+k)*HH + c];
        if (g != cur_g) {
            if (cur_g >= 0) {
                atomicAdd(&g_condsum[cur_g*HH + c], acc);
                if (c == 0) atomicAdd(&g_condcnt[cur_g], cntloc);
            }
            cur_g = g; acc = e; cntloc = 1.f;
        } else { acc += e; cntloc += 1.f; }
    }
    if (cur_g >= 0) {
        atomicAdd(&g_condsum[cur_g*HH + c], acc);
        if (c == 0) atomicAdd(&g_condcnt[cur_g], cntloc);
    }
}

// ---------------- per-graph time emb + projections ----------------
__global__ void k_graph_h(const int* __restrict__ timestep,
                          const float* __restrict__ Wt, const float* __restrict__ bt,
                          const float* __restrict__ Wc, const float* __restrict__ bc) {
    __shared__ float te[HH], pe[HH];
    const int g = blockIdx.x, c = threadIdx.x;
    float t = (float)timestep[g];
    const float L = 9.210340371976184f; // ln(10000)
    if (c < 64) te[c] = cosf(t * expf(-L * (float)c / 64.f));
    else        te[c] = sinf(t * expf(-L * (float)(c - 64) / 64.f));
    float cnt = g_condcnt[g];
    pe[c] = g_condsum[g*HH + c] / fmaxf(cnt, 1.0f);
    __syncthreads();
    float a = bt[c] + bc[c];
    #pragma unroll 8
    for (int k = 0; k < HH; k++)
        a += te[k] * Wt[k*HH + c] + pe[k] * Wc[k*HH + c];
    g_gh[g*HH + c] = a;
}

// ---------------- node embedding (+ broadcast graph term) ----------------
__global__ void k_node_emb(const float* __restrict__ x, const int* __restrict__ bmap,
                           const float* __restrict__ Wn, const float* __restrict__ bn) {
    __shared__ float xr[NDD];
    const int i = blockIdx.x, c = threadIdx.x;
    if (c < NDD) xr[c] = x[i*NDD + c];
    __syncthreads();
    float a = bn[c] + g_gh[bmap[i]*HH + c];
    #pragma unroll
    for (int k = 0; k < NDD; k++) a += xr[k] * Wn[k*HH + c];
    g_buf[0][i*HH + c] = a;
}

// ---------------- degree histogram ----------------
__global__ void k_hist(const int* __restrict__ dst) {
    int i = blockIdx.x * blockDim.x + threadIdx.x;
    int stride = gridDim.x * blockDim.x;
    for (int e = i; e < EE; e += stride) atomicAdd(&g_cnt[dst[e]], 1);
}

// ---------------- scan (row_ptr) + dinv ----------------
__global__ void k_scan() {   // 1 block, 1024 threads
    __shared__ int s[1024];
    const int t = threadIdx.x;
    int v0 = g_cnt[4*t], v1 = g_cnt[4*t+1], v2 = g_cnt[4*t+2], v3 = g_cnt[4*t+3];
    g_dinv[4*t]   = rsqrtf((float)(v0 + 1));
    g_dinv[4*t+1] = rsqrtf((float)(v1 + 1));
    g_dinv[4*t+2] = rsqrtf((float)(v2 + 1));
    g_dinv[4*t+3] = rsqrtf((float)(v3 + 1));
    int sum = v0 + v1 + v2 + v3;
    s[t] = sum; __syncthreads();
    for (int off = 1; off < 1024; off <<= 1) {
        int x = (t >= off) ? s[t - off] : 0;
        __syncthreads();
        s[t] += x;
        __syncthreads();
    }
    int excl = s[t] - sum;
    g_rowptr[4*t]   = excl;
    g_rowptr[4*t+1] = excl + v0;
    g_rowptr[4*t+2] = excl + v0 + v1;
    g_rowptr[4*t+3] = excl + v0 + v1 + v2;
    if (t == 1023) g_rowptr[NN] = excl + sum;
}

// ---------------- CSR fill ----------------
__global__ void k_fill(const int* __restrict__ src, const int* __restrict__ dst) {
    int i = blockIdx.x * blockDim.x + threadIdx.x;
    int stride = gridDim.x * blockDim.x;
    for (int e = i; e < EE; e += stride) {
        int d = dst[e];
        int pos = g_rowptr[d] + atomicAdd(&g_cur[d], 1);
        g_csr[pos] = src[e];
    }
}

// ---------------- 4096x128 @ 128x128 GEMM (buffers by template index) --------
template<int S, int D>
__global__ void k_gemm128(const float* __restrict__ W) {
    const float* __restrict__ A = g_buf[S];
    float* __restrict__ C = g_buf[D];
    __shared__ float As[8][HH];
    const int r0 = blockIdx.x * 8;
    const int c = threadIdx.x;
    #pragma unroll
    for (int r = 0; r < 8; r++) As[r][c] = A[(r0 + r)*HH + c];
    __syncthreads();
    float acc[8] = {0,0,0,0,0,0,0,0};
    #pragma unroll 4
    for (int k = 0; k < HH; k++) {
        float w = W[k*HH + c];
        #pragma unroll
        for (int r = 0; r < 8; r++) acc[r] += As[r][k] * w;
    }
    #pragma unroll
    for (int r = 0; r < 8; r++) C[(r0 + r)*HH + c] = acc[r];
}

// ---------------- GCN aggregate (gather via CSR) + bias + relu ----------------
template<int S, int D>
__global__ void k_agg(const float* __restrict__ bias) {
    const float* __restrict__ xw = g_buf[S];
    float* __restrict__ out = g_buf[D];
    const int i = blockIdx.x, c = threadIdx.x;
    const float di = g_dinv[i];
    float acc = di * xw[i*HH + c];          // self loop (outer di applied below)
    const int s0 = g_rowptr[i], s1 = g_rowptr[i+1];
    int e = s0;
    for (; e + 4 <= s1; e += 4) {
        int a0 = g_csr[e], a1 = g_csr[e+1], a2 = g_csr[e+2], a3 = g_csr[e+3];
        float w0 = g_dinv[a0], w1 = g_dinv[a1], w2 = g_dinv[a2], w3 = g_dinv[a3];
        acc += w0 * xw[a0*HH + c] + w1 * xw[a1*HH + c]
             + w2 * xw[a2*HH + c] + w3 * xw[a3*HH + c];
    }
    for (; e < s1; e++) {
        int a = g_csr[e];
        acc += g_dinv[a] * xw[a*HH + c];
    }
    float v = di * acc + bias[c];
    out[i*HH + c] = fmaxf(v, 0.f);
}

// ---------------- head: node output + edge-score vectors ----------------
__global__ void k_head(const float* __restrict__ Wo, const float* __restrict__ bo,
                       const float* __restrict__ we, float* __restrict__ out_nodes) {
    const float* __restrict__ h = g_buf[0];
    __shared__ float hr[HH];
    __shared__ float wl[4], wr[4];
    const int i = blockIdx.x, c = threadIdx.x;
    const int lane = c & 31, warp = c >> 5;
    float hv = h[i*HH + c];
    hr[c] = hv;
    float pl = hv * we[c];
    float pr = hv * we[HH + c];
    #pragma unroll
    for (int off = 16; off > 0; off >>= 1) {
        pl += __shfl_down_sync(0xffffffffu, pl, off);
        pr += __shfl_down_sync(0xffffffffu, pr, off);
    }
    if (lane == 0) { wl[warp] = pl; wr[warp] = pr; }
    __syncthreads();
    if (c == 0) g_sl[i] = wl[0] + wl[1] + wl[2] + wl[3];
    if (c == 1) g_sr[i] = wr[0] + wr[1] + wr[2] + wr[3];
    if (c < NDD) {
        float a = bo[c];
        #pragma unroll 8
        for (int k = 0; k < HH; k++) a += hr[k] * Wo[k*NDD + c];
        out_nodes[i*NDD + c] = a;
    }
}

// ---------------- all-pairs edge logits ----------------
__global__ void k_edges(const float* __restrict__ bedge, float* __restrict__ out_edges) {
    const int i = blockIdx.x;
    const int n = NN;
    const int cnt = n - 1 - i;
    if (cnt <= 0) return;
    const long long off = (long long)i * (2LL*n - i - 1) / 2;
    const float sl = g_sl[i] + bedge[0];
    float* o = out_edges + off;
    const float* sr = g_sr + i + 1;
    for (int j = threadIdx.x; j < cnt; j += blockDim.x)
        o[j] = sl + sr[j];
}

// ---------------- launch ----------------
extern "C" void kernel_launch(void* const* d_in, const int* in_sizes, int n_in,
                              void* d_out, int out_size) {
    const float* x        = (const float*)d_in[0];
    const int*   eidx     = (const int*)d_in[1];
    const int*   timestep = (const int*)d_in[2];
    const int*   bmap     = (const int*)d_in[3];
    const int*   nuc      = (const int*)d_in[4];
    const void*  central  = d_in[5];
    const void*  backbone = d_in[6];
    const float* obj_x    = (const float*)d_in[7];
    const float* obj_pos  = (const float*)d_in[8];
    const int*   obatch   = (const int*)d_in[9];
    const float* Wn = (const float*)d_in[10]; const float* bn = (const float*)d_in[11];
    const float* Wc = (const float*)d_in[12]; const float* bc = (const float*)d_in[13];
    const float* Wt = (const float*)d_in[14]; const float* bt = (const float*)d_in[15];
    const float* W1 = (const float*)d_in[16]; const float* b1 = (const float*)d_in[17];
    const float* W2 = (const float*)d_in[18]; const float* b2 = (const float*)d_in[19];
    const float* Wo = (const float*)d_in[20]; const float* bo = (const float*)d_in[21];
    const float* we = (const float*)d_in[22]; const float* be = (const float*)d_in[23];

    float* out = (float*)d_out;
    float* out_nodes = out;                 // [N, ND]
    float* out_edges = out + NN*NDD;        // [N*(N-1)/2]

    const int* esrc = eidx;
    const int* edst = eidx + EE;

    k_zero<<<64, 256>>>();
    k_detect<<<(MM + 255)/256, 256>>>((const unsigned char*)central,
                                      (const unsigned char*)backbone, MM);
    k_cond_pool<<<MM/32, HH>>>(obj_x, obj_pos, nuc, central, backbone, obatch, Wn, bn);
    k_hist<<<256, 256>>>(edst);
    k_scan<<<1, 1024>>>();
    k_fill<<<256, 256>>>(esrc, edst);
    k_graph_h<<<GG, HH>>>(timestep, Wt, bt, Wc, bc);
    k_node_emb<<<NN, HH>>>(x, bmap, Wn, bn);

    k_gemm128<0,1><<<NN/8, HH>>>(W1);
    k_agg<1,2><<<NN, HH>>>(b1);
    k_gemm128<2,1><<<NN/8, HH>>>(W2);
    k_agg<1,0><<<NN, HH>>>(b2);

    k_head<<<NN, HH>>>(Wo, bo, we, out_nodes);
    k_edges<<<NN, 256>>>(be, out_edges);
}

// round 3
// speedup vs baseline: 1.1314x; 1.1314x over previous
#include <cuda_runtime.h>
#include <math.h>

#define NN 4096
#define MM 8192
#define GG 8
#define HH 128
#define NDD 16
#define EE 131072
#define MAXD 512

// ---------------- device scratch ----------------
__device__ float g_buf[3][NN*HH];   // 1: xw scratch, 2: h1
__device__ int   g_cnt[NN];
__device__ int   g_cur[NN];
__device__ int   g_rowptr[NN+1];
__device__ int   g_csr[EE];
__device__ float g_dinv[NN];
__device__ float g_condsum[GG*HH];
__device__ float g_condcnt[GG];
__device__ float g_gh[GG*HH];
__device__ float g_sl[NN];
__device__ float g_sr[NN];
__device__ int   g_bad[2][64];      // per-block mask-layout evidence

// ================= K1: zero + mask-layout detect =================
// grid 64 x 256. Zeroes counters; each block scans 128 bytes of each mask
// and records whether any byte at idx%4!=0 is nonzero (=> byte-bool layout).
__global__ void k_prep(const unsigned char* __restrict__ p0,
                       const unsigned char* __restrict__ p1) {
    const int b = blockIdx.x, t = threadIdx.x;
    const int i = b*256 + t;
    if (i < NN) { g_cnt[i] = 0; g_cur[i] = 0; }
    if (i < GG*HH) g_condsum[i] = 0.f;
    if (i < GG) g_condcnt[i] = 0.f;
    __shared__ int bad0, bad1;
    if (t == 0) { bad0 = 0; bad1 = 0; }
    __syncthreads();
    // block b covers bytes [b*128, b*128+128)
    if (t < 128) {
        int idx = b*128 + t;
        if ((idx & 3) != 0) {
            if (p0[idx]) atomicOr(&bad0, 1);
            if (p1[idx]) atomicOr(&bad1, 1);
        }
    }
    __syncthreads();
    if (t == 0) { g_bad[0][b] = bad0; g_bad[1][b] = bad1; }
}

// ================= K2: hist + cond_pool fused =================
// blocks [0,64): degree histogram (8 edges/thread, int4 loads)
// blocks [64,320): cond pooling (32 objs/block, 128 active threads)
__global__ void k_hist_cond(const int* __restrict__ dst,
                            const float* __restrict__ obj_x, const float* __restrict__ obj_pos,
                            const int* __restrict__ nuc, const void* central, const void* backbone,
                            const int* __restrict__ obatch,
                            const float* __restrict__ Wn, const float* __restrict__ bn) {
    const int t = threadIdx.x;
    if (blockIdx.x < 64) {
        const int e0 = (blockIdx.x*256 + t) * 8;
        int4 d0 = *(const int4*)(dst + e0);
        int4 d1 = *(const int4*)(dst + e0 + 4);
        atomicAdd(&g_cnt[d0.x], 1); atomicAdd(&g_cnt[d0.y], 1);
        atomicAdd(&g_cnt[d0.z], 1); atomicAdd(&g_cnt[d0.w], 1);
        atomicAdd(&g_cnt[d1.x], 1); atomicAdd(&g_cnt[d1.y], 1);
        atomicAdd(&g_cnt[d1.z], 1); atomicAdd(&g_cnt[d1.w], 1);
        return;
    }
    // reduce layout flags (uniform block participation)
    int f0 = __syncthreads_or(t < 64 ? g_bad[0][t] : 0);
    int f1 = __syncthreads_or(t < 64 ? g_bad[1][t] : 0);
    const int fC = !f0, fB = !f1;   // 1 => int32 layout
    if (t >= 128) return;
    const int c = t;
    const int m0 = (blockIdx.x - 64) * 32;
    float acc = 0.f, cntloc = 0.f; int cur_g = -1;
    for (int mm = 0; mm < 32; mm++) {
        int m = m0 + mm;
        int nv = nuc[m];
        bool cen = fC ? (((const int*)central)[m] != 0) : (((const unsigned char*)central)[m] != 0);
        bool bb  = fB ? (((const int*)backbone)[m] != 0) : (((const unsigned char*)backbone)[m] != 0);
        bool base = !bb;
        bool cond = (nv == 0) || (cen && base) || ((nv == 2) && base);
        if (!cond) continue;
        int g = obatch[m];
        float e = bn[c];
        #pragma unroll
        for (int k = 0; k < 13; k++) e += obj_x[m*13 + k] * Wn[k*HH + c];
        #pragma unroll
        for (int k = 0; k < 3; k++)  e += obj_pos[m*3 + k] * Wn[(13+k)*HH + c];
        if (g != cur_g) {
            if (cur_g >= 0) {
                atomicAdd(&g_condsum[cur_g*HH + c], acc);
                if (c == 0) atomicAdd(&g_condcnt[cur_g], cntloc);
            }
            cur_g = g; acc = e; cntloc = 1.f;
        } else { acc += e; cntloc += 1.f; }
    }
    if (cur_g >= 0) {
        atomicAdd(&g_condsum[cur_g*HH + c], acc);
        if (c == 0) atomicAdd(&g_condcnt[cur_g], cntloc);
    }
}

// ================= K3: scan (block 0) + graph_h (blocks 1..8) =================
__global__ void k_scan_graph(const int* __restrict__ timestep,
                             const float* __restrict__ Wt, const float* __restrict__ bt,
                             const float* __restrict__ Wc, const float* __restrict__ bc) {
    if (blockIdx.x == 0) {
        __shared__ int s[1024];
        const int t = threadIdx.x;
        int v0 = g_cnt[4*t], v1 = g_cnt[4*t+1], v2 = g_cnt[4*t+2], v3 = g_cnt[4*t+3];
        g_dinv[4*t]   = rsqrtf((float)(v0 + 1));
        g_dinv[4*t+1] = rsqrtf((float)(v1 + 1));
        g_dinv[4*t+2] = rsqrtf((float)(v2 + 1));
        g_dinv[4*t+3] = rsqrtf((float)(v3 + 1));
        int sum = v0 + v1 + v2 + v3;
        s[t] = sum; __syncthreads();
        for (int off = 1; off < 1024; off <<= 1) {
            int x = (t >= off) ? s[t - off] : 0;
            __syncthreads();
            s[t] += x;
            __syncthreads();
        }
        int excl = s[t] - sum;
        g_rowptr[4*t]   = excl;
        g_rowptr[4*t+1] = excl + v0;
        g_rowptr[4*t+2] = excl + v0 + v1;
        g_rowptr[4*t+3] = excl + v0 + v1 + v2;
        if (t == 1023) g_rowptr[NN] = excl + sum;
        return;
    }
    __shared__ float te[HH], pe[HH];
    const int g = blockIdx.x - 1, c = threadIdx.x;
    if (c < HH) {
        float tv = (float)timestep[g];
        const float L = 9.210340371976184f;
        if (c < 64) te[c] = cosf(tv * expf(-L * (float)c / 64.f));
        else        te[c] = sinf(tv * expf(-L * (float)(c - 64) / 64.f));
        pe[c] = g_condsum[g*HH + c] / fmaxf(g_condcnt[g], 1.0f);
    }
    __syncthreads();
    if (c < HH) {
        float a = bt[c] + bc[c];
        #pragma unroll 8
        for (int k = 0; k < HH; k++)
            a += te[k] * Wt[k*HH + c] + pe[k] * Wc[k*HH + c];
        g_gh[g*HH + c] = a;
    }
}

// ================= GEMM core: 32 rows x 128 cols per block, 256 threads ======
// EMB=1: stage-1 computes node_emb into As (gemm1). EMB=0: loads A from g_buf[S].
// Epilogue scales by dinv[i] (fold GCN norm into xw).
template<int EMB, int S, int D>
__global__ void k_gemm(const float* __restrict__ W,
                       const float* __restrict__ x, const int* __restrict__ bmap,
                       const float* __restrict__ Wn, const float* __restrict__ bn,
                       int blk0) {
    const int blk = blockIdx.x - blk0;
    if (blk < 0) return;   // (never happens in plain gemm launches)
    __shared__ float As[32][HH];
    const int i0 = blk * 32;
    const int t = threadIdx.x;
    const int c = t & 127, rg = t >> 7;       // rg in {0,1}, rows rg*16..rg*16+15

    if (EMB) {
        __shared__ float Wns[NDD*HH];
        __shared__ float bns[HH];
        __shared__ float xr[32][NDD];
        __shared__ int   gidx[32];
        #pragma unroll
        for (int j = 0; j < NDD*HH/256; j++) Wns[t + 256*j] = Wn[t + 256*j];
        if (t < HH) bns[t] = bn[t];
        if (t < 32) gidx[t] = bmap[i0 + t];
        #pragma unroll
        for (int j = 0; j < 2; j++) {
            int idx = t + 256*j;  // 512 = 32*16 contiguous floats
            ((float*)xr)[idx] = x[i0*NDD + idx];
        }
        __syncthreads();
        float wnk[NDD];
        #pragma unroll
        for (int k = 0; k < NDD; k++) wnk[k] = Wns[k*HH + c];
        #pragma unroll 4
        for (int r16 = 0; r16 < 16; r16++) {
            int r = rg*16 + r16;
            float a = bns[c] + g_gh[gidx[r]*HH + c];
            #pragma unroll
            for (int k = 0; k < NDD; k++) a += xr[r][k] * wnk[k];
            As[r][c] = a;
        }
    } else {
        const float4* src = (const float4*)(g_buf[S] + i0*HH);
        float4* dstp = (float4*)As;
        #pragma unroll
        for (int j = 0; j < 4; j++) dstp[t + 256*j] = src[t + 256*j];
    }
    __syncthreads();

    float acc[16];
    #pragma unroll
    for (int r = 0; r < 16; r++) acc[r] = 0.f;
    const float4* As4 = (const float4*)As;   // As4[r*32 + k4]
    for (int k0 = 0; k0 < HH; k0 += 4) {
        float w0 = W[(k0+0)*HH + c];
        float w1 = W[(k0+1)*HH + c];
        float w2 = W[(k0+2)*HH + c];
        float w3 = W[(k0+3)*HH + c];
        int k4 = k0 >> 2;
        #pragma unroll
        for (int r = 0; r < 16; r++) {
            float4 a4 = As4[(rg*16 + r)*32 + k4];
            acc[r] += a4.x*w0 + a4.y*w1 + a4.z*w2 + a4.w*w3;
        }
    }
    #pragma unroll
    for (int r = 0; r < 16; r++) {
        int i = i0 + rg*16 + r;
        g_buf[D][i*HH + c] = g_dinv[i] * acc[r];
    }
}

// ================= K4: CSR fill + gemm1 fused =================
// blocks [0,64): fill. blocks [64,192): gemm1 (with fused node embedding).
__global__ void k_fill_gemm1(const int* __restrict__ src, const int* __restrict__ dst,
                             const float* __restrict__ W1,
                             const float* __restrict__ x, const int* __restrict__ bmap,
                             const float* __restrict__ Wn, const float* __restrict__ bn);

// helper so fill+gemm can live in one kernel: replicate gemm body via function
template<int EMB, int S, int D>
__device__ __forceinline__ void gemm_body(int blk, const float* __restrict__ W,
                                          const float* __restrict__ x, const int* __restrict__ bmap,
                                          const float* __restrict__ Wn, const float* __restrict__ bn) {
    __shared__ float As[32][HH];
    const int i0 = blk * 32;
    const int t = threadIdx.x;
    const int c = t & 127, rg = t >> 7;
    if (EMB) {
        __shared__ float Wns[NDD*HH];
        __shared__ float bns[HH];
        __shared__ float xr[32][NDD];
        __shared__ int   gidx[32];
        #pragma unroll
        for (int j = 0; j < NDD*HH/256; j++) Wns[t + 256*j] = Wn[t + 256*j];
        if (t < HH) bns[t] = bn[t];
        if (t < 32) gidx[t] = bmap[i0 + t];
        #pragma unroll
        for (int j = 0; j < 2; j++) {
            int idx = t + 256*j;
            ((float*)xr)[idx] = x[i0*NDD + idx];
        }
        __syncthreads();
        float wnk[NDD];
        #pragma unroll
        for (int k = 0; k < NDD; k++) wnk[k] = Wns[k*HH + c];
        #pragma unroll 4
        for (int r16 = 0; r16 < 16; r16++) {
            int r = rg*16 + r16;
            float a = bns[c] + g_gh[gidx[r]*HH + c];
            #pragma unroll
            for (int k = 0; k < NDD; k++) a += xr[r][k] * wnk[k];
            As[r][c] = a;
        }
    } else {
        const float4* srcp = (const float4*)(g_buf[S] + i0*HH);
        float4* dstp = (float4*)As;
        #pragma unroll
        for (int j = 0; j < 4; j++) dstp[t + 256*j] = srcp[t + 256*j];
    }
    __syncthreads();
    float acc[16];
    #pragma unroll
    for (int r = 0; r < 16; r++) acc[r] = 0.f;
    const float4* As4 = (const float4*)As;
    for (int k0 = 0; k0 < HH; k0 += 4) {
        float w0 = W[(k0+0)*HH + c];
        float w1 = W[(k0+1)*HH + c];
        float w2 = W[(k0+2)*HH + c];
        float w3 = W[(k0+3)*HH + c];
        int k4 = k0 >> 2;
        #pragma unroll
        for (int r = 0; r < 16; r++) {
            float4 a4 = As4[(rg*16 + r)*32 + k4];
            acc[r] += a4.x*w0 + a4.y*w1 + a4.z*w2 + a4.w*w3;
        }
    }
    #pragma unroll
    for (int r = 0; r < 16; r++) {
        int i = i0 + rg*16 + r;
        g_buf[D][i*HH + c] = g_dinv[i] * acc[r];
    }
}

__global__ void k_fill_gemm1(const int* __restrict__ src, const int* __restrict__ dst,
                             const float* __restrict__ W1,
                             const float* __restrict__ x, const int* __restrict__ bmap,
                             const float* __restrict__ Wn, const float* __restrict__ bn) {
    if (blockIdx.x < 64) {
        const int t = threadIdx.x;
        const int e0 = (blockIdx.x*256 + t) * 8;
        int4 s0 = *(const int4*)(src + e0);
        int4 s1 = *(const int4*)(src + e0 + 4);
        int4 d0 = *(const int4*)(dst + e0);
        int4 d1 = *(const int4*)(dst + e0 + 4);
        g_csr[g_rowptr[d0.x] + atomicAdd(&g_cur[d0.x], 1)] = s0.x;
        g_csr[g_rowptr[d0.y] + atomicAdd(&g_cur[d0.y], 1)] = s0.y;
        g_csr[g_rowptr[d0.z] + atomicAdd(&g_cur[d0.z], 1)] = s0.z;
        g_csr[g_rowptr[d0.w] + atomicAdd(&g_cur[d0.w], 1)] = s0.w;
        g_csr[g_rowptr[d1.x] + atomicAdd(&g_cur[d1.x], 1)] = s1.x;
        g_csr[g_rowptr[d1.y] + atomicAdd(&g_cur[d1.y], 1)] = s1.y;
        g_csr[g_rowptr[d1.z] + atomicAdd(&g_cur[d1.z], 1)] = s1.z;
        g_csr[g_rowptr[d1.w] + atomicAdd(&g_cur[d1.w], 1)] = s1.w;
        return;
    }
    gemm_body<1, 0, 1>(blockIdx.x - 64, W1, x, bmap, Wn, bn);
}

__global__ void k_gemm2(const float* __restrict__ W2) {
    gemm_body<0, 2, 1>(blockIdx.x, W2, nullptr, nullptr, nullptr, nullptr);
}

// ================= agg: 2 nodes/block, 128 threads each, smem CSR =============
// xw is pre-scaled by dinv. out = dinv[i]*(sum + self) + bias, relu.
template<int S, int D>
__global__ void k_agg(const float* __restrict__ bias) {
    const float* __restrict__ xw = g_buf[S];
    __shared__ int scsr[2][MAXD];
    const int t = threadIdx.x;
    const int grp = t >> 7, lt = t & 127;
    const int i = blockIdx.x*2 + grp;
    const int s0 = g_rowptr[i], s1 = g_rowptr[i+1];
    const int deg = s1 - s0;
    for (int j = lt; j < deg && j < MAXD; j += 128) scsr[grp][j] = g_csr[s0 + j];
    __syncthreads();
    const int c = lt;
    float acc = xw[i*HH + c];          // self term (already dinv-scaled)
    int j = 0;
    const int dlim = deg < MAXD ? deg : MAXD;
    for (; j + 4 <= dlim; j += 4) {
        int a0 = scsr[grp][j], a1 = scsr[grp][j+1], a2 = scsr[grp][j+2], a3 = scsr[grp][j+3];
        acc += xw[a0*HH + c] + xw[a1*HH + c] + xw[a2*HH + c] + xw[a3*HH + c];
    }
    for (; j < dlim; j++) acc += xw[scsr[grp][j]*HH + c];
    for (int e = s0 + dlim; e < s1; e++) acc += xw[g_csr[e]*HH + c];  // overflow fallback
    float v = g_dinv[i] * acc + bias[c];
    g_buf[D][i*HH + c] = fmaxf(v, 0.f);
}

// ================= agg2 + head fused =================
__global__ void k_agg_head(const float* __restrict__ bias,
                           const float* __restrict__ Wo, const float* __restrict__ bo,
                           const float* __restrict__ we, float* __restrict__ out_nodes) {
    const float* __restrict__ xw = g_buf[1];
    __shared__ int scsr[2][MAXD];
    __shared__ float hr[2][HH];
    __shared__ float wl[2][4], wr[2][4];
    const int t = threadIdx.x;
    const int grp = t >> 7, lt = t & 127;
    const int i = blockIdx.x*2 + grp;
    const int s0 = g_rowptr[i], s1 = g_rowptr[i+1];
    const int deg = s1 - s0;
    for (int j = lt; j < deg && j < MAXD; j += 128) scsr[grp][j] = g_csr[s0 + j];
    __syncthreads();
    const int c = lt;
    float acc = xw[i*HH + c];
    int j = 0;
    const int dlim = deg < MAXD ? deg : MAXD;
    for (; j + 4 <= dlim; j += 4) {
        int a0 = scsr[grp][j], a1 = scsr[grp][j+1], a2 = scsr[grp][j+2], a3 = scsr[grp][j+3];
        acc += xw[a0*HH + c] + xw[a1*HH + c] + xw[a2*HH + c] + xw[a3*HH + c];
    }
    for (; j < dlim; j++) acc += xw[scsr[grp][j]*HH + c];
    for (int e = s0 + dlim; e < s1; e++) acc += xw[g_csr[e]*HH + c];
    float hv = fmaxf(g_dinv[i] * acc + bias[c], 0.f);
    hr[grp][c] = hv;
    // edge-score partial reductions
    float pl = hv * we[c];
    float pr = hv * we[HH + c];
    const int lane = lt & 31, w = lt >> 5;
    #pragma unroll
    for (int off = 16; off > 0; off >>= 1) {
        pl += __shfl_down_sync(0xffffffffu, pl, off);
        pr += __shfl_down_sync(0xffffffffu, pr, off);
    }
    if (lane == 0) { wl[grp][w] = pl; wr[grp][w] = pr; }
    __syncthreads();
    if (lt == 0) g_sl[i] = wl[grp][0] + wl[grp][1] + wl[grp][2] + wl[grp][3];
    if (lt == 1) g_sr[i] = wr[grp][0] + wr[grp][1] + wr[grp][2] + wr[grp][3];
    if (lt < NDD) {
        float a = bo[lt];
        #pragma unroll 8
        for (int k = 0; k < HH; k++) a += hr[grp][k] * Wo[k*NDD + lt];
        out_nodes[i*NDD + lt] = a;
    }
}

// ================= edges: float4 stores =================
__global__ void k_edges(const float* __restrict__ bedge, float* __restrict__ out_edges) {
    const int i = blockIdx.x;
    const int cnt = NN - 1 - i;
    if (cnt <= 0) return;
    const long long off = (long long)i * (2LL*NN - i - 1) / 2;
    const float sl = g_sl[i] + bedge[0];
    float* o = out_edges + off;
    const float* sr = g_sr + i + 1;
    const int t = threadIdx.x;
    const int pre0 = (int)((4 - (off & 3)) & 3);
    const int pre = pre0 < cnt ? pre0 : cnt;
    if (t < pre) o[t] = sl + sr[t];
    const int nv = (cnt - pre) >> 2;
    float4* o4 = (float4*)(o + pre);
    for (int v = t; v < nv; v += 256) {
        int j = pre + v*4;
        float4 r;
        r.x = sl + sr[j];   r.y = sl + sr[j+1];
        r.z = sl + sr[j+2]; r.w = sl + sr[j+3];
        o4[v] = r;
    }
    const int tail0 = pre + nv*4;
    const int rem = cnt - tail0;
    if (t < rem) o[tail0 + t] = sl + sr[tail0 + t];
}

// ================= launch =================
extern "C" void kernel_launch(void* const* d_in, const int* in_sizes, int n_in,
                              void* d_out, int out_size) {
    const float* x        = (const float*)d_in[0];
    const int*   eidx     = (const int*)d_in[1];
    const int*   timestep = (const int*)d_in[2];
    const int*   bmap     = (const int*)d_in[3];
    const int*   nuc      = (const int*)d_in[4];
    const void*  central  = d_in[5];
    const void*  backbone = d_in[6];
    const float* obj_x    = (const float*)d_in[7];
    const float* obj_pos  = (const float*)d_in[8];
    const int*   obatch   = (const int*)d_in[9];
    const float* Wn = (const float*)d_in[10]; const float* bn = (const float*)d_in[11];
    const float* Wc = (const float*)d_in[12]; const float* bc = (const float*)d_in[13];
    const float* Wt = (const float*)d_in[14]; const float* bt = (const float*)d_in[15];
    const float* W1 = (const float*)d_in[16]; const float* b1 = (const float*)d_in[17];
    const float* W2 = (const float*)d_in[18]; const float* b2 = (const float*)d_in[19];
    const float* Wo = (const float*)d_in[20]; const float* bo = (const float*)d_in[21];
    const float* we = (const float*)d_in[22]; const float* be = (const float*)d_in[23];

    float* out = (float*)d_out;
    float* out_nodes = out;
    float* out_edges = out + NN*NDD;

    const int* esrc = eidx;
    const int* edst = eidx + EE;

    k_prep<<<64, 256>>>((const unsigned char*)central, (const unsigned char*)backbone);
    k_hist_cond<<<320, 256>>>(edst, obj_x, obj_pos, nuc, central, backbone, obatch, Wn, bn);
    k_scan_graph<<<9, 1024>>>(timestep, Wt, bt, Wc, bc);
    k_fill_gemm1<<<64 + NN/32, 256>>>(esrc, edst, W1, x, bmap, Wn, bn);
    k_agg<1, 2><<<NN/2, 256>>>(b1);
    k_gemm2<<<NN/32, 256>>>(W2);
    k_agg_head<<<NN/2, 256>>>(b2, Wo, bo, we, out_nodes);
    k_edges<<<NN, 256>>>(be, out_edges);
}

// round 4
// speedup vs baseline: 1.2435x; 1.0991x over previous
#include <cuda_runtime.h>
#include <math.h>

#define NN 4096
#define MM 8192
#define GG 8
#define HH 128
#define NDD 16
#define EE 131072

// ---------------- device scratch ----------------
__device__ float g_buf[3][NN*HH];   // 1: xw scratch, 2: h1
__device__ int   g_cnt[NN];
__device__ int   g_cur[NN];
__device__ int   g_rowptr[NN+1];
__device__ int   g_csr[EE];
__device__ float g_dinv[NN];
__device__ float g_condsum[GG*HH];
__device__ float g_condcnt[GG];
__device__ float g_gh[GG*HH];
__device__ float g_sl[NN];
__device__ float g_sr[NN];
__device__ int   g_bad[2][64];

// ================= K1: zero + mask-layout detect =================
__global__ void k_prep(const unsigned char* __restrict__ p0,
                       const unsigned char* __restrict__ p1) {
    const int b = blockIdx.x, t = threadIdx.x;
    const int i = b*256 + t;
    if (i < NN) { g_cnt[i] = 0; g_cur[i] = 0; }
    if (i < GG*HH) g_condsum[i] = 0.f;
    if (i < GG) g_condcnt[i] = 0.f;
    __shared__ int bad0, bad1;
    if (t == 0) { bad0 = 0; bad1 = 0; }
    __syncthreads();
    if (t < 128) {
        int idx = b*128 + t;
        if ((idx & 3) != 0) {
            if (p0[idx]) atomicOr(&bad0, 1);
            if (p1[idx]) atomicOr(&bad1, 1);
        }
    }
    __syncthreads();
    if (t == 0) { g_bad[0][b] = bad0; g_bad[1][b] = bad1; }
}

// ================= K2: hist + cond_pool fused =================
__global__ void k_hist_cond(const int* __restrict__ dst,
                            const float* __restrict__ obj_x, const float* __restrict__ obj_pos,
                            const int* __restrict__ nuc, const void* central, const void* backbone,
                            const int* __restrict__ obatch,
                            const float* __restrict__ Wn, const float* __restrict__ bn) {
    const int t = threadIdx.x;
    if (blockIdx.x < 64) {
        const int e0 = (blockIdx.x*256 + t) * 8;
        int4 d0 = *(const int4*)(dst + e0);
        int4 d1 = *(const int4*)(dst + e0 + 4);
        atomicAdd(&g_cnt[d0.x], 1); atomicAdd(&g_cnt[d0.y], 1);
        atomicAdd(&g_cnt[d0.z], 1); atomicAdd(&g_cnt[d0.w], 1);
        atomicAdd(&g_cnt[d1.x], 1); atomicAdd(&g_cnt[d1.y], 1);
        atomicAdd(&g_cnt[d1.z], 1); atomicAdd(&g_cnt[d1.w], 1);
        return;
    }
    int f0 = __syncthreads_or(t < 64 ? g_bad[0][t] : 0);
    int f1 = __syncthreads_or(t < 64 ? g_bad[1][t] : 0);
    const int fC = !f0, fB = !f1;
    if (t >= 128) return;
    const int c = t;
    const int m0 = (blockIdx.x - 64) * 32;
    float acc = 0.f, cntloc = 0.f; int cur_g = -1;
    for (int mm = 0; mm < 32; mm++) {
        int m = m0 + mm;
        int nv = nuc[m];
        bool cen = fC ? (((const int*)central)[m] != 0) : (((const unsigned char*)central)[m] != 0);
        bool bb  = fB ? (((const int*)backbone)[m] != 0) : (((const unsigned char*)backbone)[m] != 0);
        bool base = !bb;
        bool cond = (nv == 0) || (cen && base) || ((nv == 2) && base);
        if (!cond) continue;
        int g = obatch[m];
        float e = bn[c];
        #pragma unroll
        for (int k = 0; k < 13; k++) e += obj_x[m*13 + k] * Wn[k*HH + c];
        #pragma unroll
        for (int k = 0; k < 3; k++)  e += obj_pos[m*3 + k] * Wn[(13+k)*HH + c];
        if (g != cur_g) {
            if (cur_g >= 0) {
                atomicAdd(&g_condsum[cur_g*HH + c], acc);
                if (c == 0) atomicAdd(&g_condcnt[cur_g], cntloc);
            }
            cur_g = g; acc = e; cntloc = 1.f;
        } else { acc += e; cntloc += 1.f; }
    }
    if (cur_g >= 0) {
        atomicAdd(&g_condsum[cur_g*HH + c], acc);
        if (c == 0) atomicAdd(&g_condcnt[cur_g], cntloc);
    }
}

// ================= K3: scan (block 0) + graph_h (blocks 1..8) =================
__global__ void k_scan_graph(const int* __restrict__ timestep,
                             const float* __restrict__ Wt, const float* __restrict__ bt,
                             const float* __restrict__ Wc, const float* __restrict__ bc) {
    if (blockIdx.x == 0) {
        __shared__ int s[1024];
        const int t = threadIdx.x;
        int v0 = g_cnt[4*t], v1 = g_cnt[4*t+1], v2 = g_cnt[4*t+2], v3 = g_cnt[4*t+3];
        g_dinv[4*t]   = rsqrtf((float)(v0 + 1));
        g_dinv[4*t+1] = rsqrtf((float)(v1 + 1));
        g_dinv[4*t+2] = rsqrtf((float)(v2 + 1));
        g_dinv[4*t+3] = rsqrtf((float)(v3 + 1));
        int sum = v0 + v1 + v2 + v3;
        s[t] = sum; __syncthreads();
        for (int off = 1; off < 1024; off <<= 1) {
            int x = (t >= off) ? s[t - off] : 0;
            __syncthreads();
            s[t] += x;
            __syncthreads();
        }
        int excl = s[t] - sum;
        g_rowptr[4*t]   = excl;
        g_rowptr[4*t+1] = excl + v0;
        g_rowptr[4*t+2] = excl + v0 + v1;
        g_rowptr[4*t+3] = excl + v0 + v1 + v2;
        if (t == 1023) g_rowptr[NN] = excl + sum;
        return;
    }
    __shared__ float te[HH], pe[HH];
    const int g = blockIdx.x - 1, c = threadIdx.x;
    if (c < HH) {
        float tv = (float)timestep[g];
        const float L = 9.210340371976184f;
        if (c < 64) te[c] = cosf(tv * expf(-L * (float)c / 64.f));
        else        te[c] = sinf(tv * expf(-L * (float)(c - 64) / 64.f));
        pe[c] = g_condsum[g*HH + c] / fmaxf(g_condcnt[g], 1.0f);
    }
    __syncthreads();
    if (c < HH) {
        float a = bt[c] + bc[c];
        #pragma unroll 8
        for (int k = 0; k < HH; k++)
            a += te[k] * Wt[k*HH + c] + pe[k] * Wc[k*HH + c];
        g_gh[g*HH + c] = a;
    }
}

// ================= GEMM body: 16 rows x 128 cols/block, W staged in smem =====
// 256 threads = c(0..127) x rg(0..1); thread computes 8 rows at column c.
// Epilogue: scale by dinv[i] (folds GCN norm into xw).
template<int EMB, int S, int D>
__device__ __forceinline__ void gemm_body(int blk, const float* __restrict__ W,
                                          const float* __restrict__ x, const int* __restrict__ bmap,
                                          const float* __restrict__ Wn, const float* __restrict__ bn) {
    __shared__ float As[16][HH];
    __shared__ float Ws[32][HH];
    const int i0 = blk * 16;
    const int t = threadIdx.x;
    const int c = t & 127, rg = t >> 7;

    if (EMB) {
        __shared__ float Wns[NDD*HH];
        __shared__ float bns[HH];
        __shared__ float xr[16][NDD];
        __shared__ int   gidx[16];
        #pragma unroll
        for (int j = 0; j < NDD*HH/256; j++) Wns[t + 256*j] = Wn[t + 256*j];
        if (t < HH) bns[t] = bn[t];
        if (t < 16) gidx[t] = bmap[i0 + t];
        ((float*)xr)[t] = x[i0*NDD + t];    // 16*16 = 256 floats
        __syncthreads();
        float wnk[NDD];
        #pragma unroll
        for (int k = 0; k < NDD; k++) wnk[k] = Wns[k*HH + c];
        #pragma unroll
        for (int r8 = 0; r8 < 8; r8++) {
            int r = rg*8 + r8;
            float a = bns[c] + g_gh[gidx[r]*HH + c];
            #pragma unroll
            for (int k = 0; k < NDD; k++) a += xr[r][k] * wnk[k];
            As[r][c] = a;
        }
    } else {
        const float4* srcp = (const float4*)(g_buf[S] + i0*HH);
        float4* dstp = (float4*)As;
        dstp[t]       = srcp[t];
        dstp[t + 256] = srcp[t + 256];
    }

    float acc[8] = {0,0,0,0,0,0,0,0};
    const float4* As4 = (const float4*)As;
    for (int kt = 0; kt < HH; kt += 32) {
        __syncthreads();                      // As ready / Ws free
        const float4* w4 = (const float4*)(W + kt*HH);
        float4* ws4 = (float4*)Ws;
        #pragma unroll
        for (int j = 0; j < 4; j++) ws4[t + 256*j] = w4[t + 256*j];
        __syncthreads();
        #pragma unroll
        for (int k0 = 0; k0 < 32; k0 += 4) {
            float w0 = Ws[k0][c], w1 = Ws[k0+1][c], w2 = Ws[k0+2][c], w3 = Ws[k0+3][c];
            int k4 = (kt + k0) >> 2;
            #pragma unroll
            for (int r = 0; r < 8; r++) {
                float4 a4 = As4[(rg*8 + r)*32 + k4];
                acc[r] += a4.x*w0 + a4.y*w1 + a4.z*w2 + a4.w*w3;
            }
        }
    }
    #pragma unroll
    for (int r = 0; r < 8; r++) {
        int i = i0 + rg*8 + r;
        g_buf[D][i*HH + c] = g_dinv[i] * acc[r];
    }
}

// ================= K4: CSR fill + gemm1 (fused node embedding) ================
__global__ void k_fill_gemm1(const int* __restrict__ src, const int* __restrict__ dst,
                             const float* __restrict__ W1,
                             const float* __restrict__ x, const int* __restrict__ bmap,
                             const float* __restrict__ Wn, const float* __restrict__ bn) {
    if (blockIdx.x < 64) {
        const int t = threadIdx.x;
        const int e0 = (blockIdx.x*256 + t) * 8;
        int4 s0 = *(const int4*)(src + e0);
        int4 s1 = *(const int4*)(src + e0 + 4);
        int4 d0 = *(const int4*)(dst + e0);
        int4 d1 = *(const int4*)(dst + e0 + 4);
        g_csr[g_rowptr[d0.x] + atomicAdd(&g_cur[d0.x], 1)] = s0.x;
        g_csr[g_rowptr[d0.y] + atomicAdd(&g_cur[d0.y], 1)] = s0.y;
        g_csr[g_rowptr[d0.z] + atomicAdd(&g_cur[d0.z], 1)] = s0.z;
        g_csr[g_rowptr[d0.w] + atomicAdd(&g_cur[d0.w], 1)] = s0.w;
        g_csr[g_rowptr[d1.x] + atomicAdd(&g_cur[d1.x], 1)] = s1.x;
        g_csr[g_rowptr[d1.y] + atomicAdd(&g_cur[d1.y], 1)] = s1.y;
        g_csr[g_rowptr[d1.z] + atomicAdd(&g_cur[d1.z], 1)] = s1.z;
        g_csr[g_rowptr[d1.w] + atomicAdd(&g_cur[d1.w], 1)] = s1.w;
        return;
    }
    gemm_body<1, 0, 1>(blockIdx.x - 64, W1, x, bmap, Wn, bn);
}

__global__ void k_gemm2(const float* __restrict__ W2) {
    gemm_body<0, 2, 1>(blockIdx.x, W2, nullptr, nullptr, nullptr, nullptr);
}

// ================= agg: warp-per-node, float4 lanes ===========================
// xw pre-scaled by dinv. out = relu(dinv[i]*(self + sum) + bias)
template<int S, int D>
__global__ void k_aggW(const float* __restrict__ bias) {
    const int i = (blockIdx.x * blockDim.x + threadIdx.x) >> 5;
    if (i >= NN) return;
    const int lane = threadIdx.x & 31;
    const float4* __restrict__ xw = (const float4*)g_buf[S];
    float4 acc = xw[i*32 + lane];
    const int s0 = g_rowptr[i], s1 = g_rowptr[i+1];
    int e = s0;
    for (; e + 4 <= s1; e += 4) {
        int a0 = g_csr[e], a1 = g_csr[e+1], a2 = g_csr[e+2], a3 = g_csr[e+3];
        float4 v0 = xw[a0*32 + lane], v1 = xw[a1*32 + lane];
        float4 v2 = xw[a2*32 + lane], v3 = xw[a3*32 + lane];
        acc.x += (v0.x + v1.x) + (v2.x + v3.x);
        acc.y += (v0.y + v1.y) + (v2.y + v3.y);
        acc.z += (v0.z + v1.z) + (v2.z + v3.z);
        acc.w += (v0.w + v1.w) + (v2.w + v3.w);
    }
    for (; e < s1; e++) {
        float4 v = xw[g_csr[e]*32 + lane];
        acc.x += v.x; acc.y += v.y; acc.z += v.z; acc.w += v.w;
    }
    const float di = g_dinv[i];
    const float4 b4 = ((const float4*)bias)[lane];
    float4 o;
    o.x = fmaxf(di*acc.x + b4.x, 0.f);
    o.y = fmaxf(di*acc.y + b4.y, 0.f);
    o.z = fmaxf(di*acc.z + b4.z, 0.f);
    o.w = fmaxf(di*acc.w + b4.w, 0.f);
    ((float4*)g_buf[D])[i*32 + lane] = o;
}

// ================= agg2 + head fused (warp-per-node, h stays in regs) =========
__global__ void k_agg_head(const float* __restrict__ bias,
                           const float* __restrict__ Wo, const float* __restrict__ bo,
                           const float* __restrict__ we, float* __restrict__ out_nodes) {
    const int i = (blockIdx.x * blockDim.x + threadIdx.x) >> 5;
    if (i >= NN) return;
    const int lane = threadIdx.x & 31;
    const float4* __restrict__ xw = (const float4*)g_buf[1];
    float4 acc = xw[i*32 + lane];
    const int s0 = g_rowptr[i], s1 = g_rowptr[i+1];
    int e = s0;
    for (; e + 4 <= s1; e += 4) {
        int a0 = g_csr[e], a1 = g_csr[e+1], a2 = g_csr[e+2], a3 = g_csr[e+3];
        float4 v0 = xw[a0*32 + lane], v1 = xw[a1*32 + lane];
        float4 v2 = xw[a2*32 + lane], v3 = xw[a3*32 + lane];
        acc.x += (v0.x + v1.x) + (v2.x + v3.x);
        acc.y += (v0.y + v1.y) + (v2.y + v3.y);
        acc.z += (v0.z + v1.z) + (v2.z + v3.z);
        acc.w += (v0.w + v1.w) + (v2.w + v3.w);
    }
    for (; e < s1; e++) {
        float4 v = xw[g_csr[e]*32 + lane];
        acc.x += v.x; acc.y += v.y; acc.z += v.z; acc.w += v.w;
    }
    const float di = g_dinv[i];
    const float4 b4 = ((const float4*)bias)[lane];
    float4 h;
    h.x = fmaxf(di*acc.x + b4.x, 0.f);
    h.y = fmaxf(di*acc.y + b4.y, 0.f);
    h.z = fmaxf(di*acc.z + b4.z, 0.f);
    h.w = fmaxf(di*acc.w + b4.w, 0.f);

    // edge-score dots
    const float4 wl4 = ((const float4*)we)[lane];
    const float4 wr4 = ((const float4*)we)[32 + lane];
    float pl = h.x*wl4.x + h.y*wl4.y + h.z*wl4.z + h.w*wl4.w;
    float pr = h.x*wr4.x + h.y*wr4.y + h.z*wr4.z + h.w*wr4.w;

    // node output: p[c] = sum_k h[k]*Wo[k][c], k = lane*4+j
    float p[NDD];
    #pragma unroll
    for (int c = 0; c < NDD; c++) p[c] = 0.f;
    const float4* Wo4 = (const float4*)Wo;     // Wo[128][16] -> 4 float4 per row
    float hv[4] = {h.x, h.y, h.z, h.w};
    #pragma unroll
    for (int j = 0; j < 4; j++) {
        int k = lane*4 + j;
        #pragma unroll
        for (int c4 = 0; c4 < 4; c4++) {
            float4 w = Wo4[k*4 + c4];
            p[c4*4+0] += hv[j]*w.x; p[c4*4+1] += hv[j]*w.y;
            p[c4*4+2] += hv[j]*w.z; p[c4*4+3] += hv[j]*w.w;
        }
    }
    #pragma unroll
    for (int off = 16; off > 0; off >>= 1) {
        pl += __shfl_down_sync(0xffffffffu, pl, off);
        pr += __shfl_down_sync(0xffffffffu, pr, off);
        #pragma unroll
        for (int c = 0; c < NDD; c++)
            p[c] += __shfl_down_sync(0xffffffffu, p[c], off);
    }
    if (lane == 0) {
        g_sl[i] = pl;
        g_sr[i] = pr;
        float4* on4 = (float4*)(out_nodes + i*NDD);
        const float4* bo4 = (const float4*)bo;
        #pragma unroll
        for (int c4 = 0; c4 < 4; c4++) {
            float4 b = bo4[c4];
            float4 v;
            v.x = p[c4*4+0] + b.x; v.y = p[c4*4+1] + b.y;
            v.z = p[c4*4+2] + b.z; v.w = p[c4*4+3] + b.w;
            on4[c4] = v;
        }
    }
}

// ================= edges: float4 stores =================
__global__ void k_edges(const float* __restrict__ bedge, float* __restrict__ out_edges) {
    const int i = blockIdx.x;
    const int cnt = NN - 1 - i;
    if (cnt <= 0) return;
    const long long off = (long long)i * (2LL*NN - i - 1) / 2;
    const float sl = g_sl[i] + bedge[0];
    float* o = out_edges + off;
    const float* sr = g_sr + i + 1;
    const int t = threadIdx.x;
    const int pre0 = (int)((4 - (off & 3)) & 3);
    const int pre = pre0 < cnt ? pre0 : cnt;
    if (t < pre) o[t] = sl + sr[t];
    const int nv = (cnt - pre) >> 2;
    float4* o4 = (float4*)(o + pre);
    for (int v = t; v < nv; v += 256) {
        int j = pre + v*4;
        float4 r;
        r.x = sl + sr[j];   r.y = sl + sr[j+1];
        r.z = sl + sr[j+2]; r.w = sl + sr[j+3];
        o4[v] = r;
    }
    const int tail0 = pre + nv*4;
    const int rem = cnt - tail0;
    if (t < rem) o[tail0 + t] = sl + sr[tail0 + t];
}

// ================= launch =================
extern "C" void kernel_launch(void* const* d_in, const int* in_sizes, int n_in,
                              void* d_out, int out_size) {
    const float* x        = (const float*)d_in[0];
    const int*   eidx     = (const int*)d_in[1];
    const int*   timestep = (const int*)d_in[2];
    const int*   bmap     = (const int*)d_in[3];
    const int*   nuc      = (const int*)d_in[4];
    const void*  central  = d_in[5];
    const void*  backbone = d_in[6];
    const float* obj_x    = (const float*)d_in[7];
    const float* obj_pos  = (const float*)d_in[8];
    const int*   obatch   = (const int*)d_in[9];
    const float* Wn = (const float*)d_in[10]; const float* bn = (const float*)d_in[11];
    const float* Wc = (const float*)d_in[12]; const float* bc = (const float*)d_in[13];
    const float* Wt = (const float*)d_in[14]; const float* bt = (const float*)d_in[15];
    const float* W1 = (const float*)d_in[16]; const float* b1 = (const float*)d_in[17];
    const float* W2 = (const float*)d_in[18]; const float* b2 = (const float*)d_in[19];
    const float* Wo = (const float*)d_in[20]; const float* bo = (const float*)d_in[21];
    const float* we = (const float*)d_in[22]; const float* be = (const float*)d_in[23];

    float* out = (float*)d_out;
    float* out_nodes = out;
    float* out_edges = out + NN*NDD;

    const int* esrc = eidx;
    const int* edst = eidx + EE;

    k_prep<<<64, 256>>>((const unsigned char*)central, (const unsigned char*)backbone);
    k_hist_cond<<<320, 256>>>(edst, obj_x, obj_pos, nuc, central, backbone, obatch, Wn, bn);
    k_scan_graph<<<9, 1024>>>(timestep, Wt, bt, Wc, bc);
    k_fill_gemm1<<<64 + NN/16, 256>>>(esrc, edst, W1, x, bmap, Wn, bn);
    k_aggW<1, 2><<<NN*32/256, 256>>>(b1);
    k_gemm2<<<NN/16, 256>>>(W2);
    k_agg_head<<<NN*32/256, 256>>>(b2, Wo, bo, we, out_nodes);
    k_edges<<<NN, 256>>>(be, out_edges);
}

// round 5
// speedup vs baseline: 1.2474x; 1.0031x over previous
#include <cuda_runtime.h>
#include <math.h>

#define NN 4096
#define MM 8192
#define GG 8
#define HH 128
#define NDD 16
#define EE 131072

// ---------------- device scratch ----------------
__device__ float g_buf[2][NN*HH];   // 0: xw1, 1: xw2
__device__ int   g_cnt[NN];         // zeroed by k_scan after use (self-cleaning)
__device__ int   g_rowptr[NN+1];    // doubles as fill cursor (consumed semantics)
__device__ int   g_csr[EE];
__device__ float g_dinv[NN];
__device__ float g_condsum[GG*HH];  // zeroed by k_graph blocks after use
__device__ float g_condcnt[GG];
__device__ float g_gh[GG*HH];
__device__ float g_sl[NN];
__device__ float g_sr[NN];
__device__ int   g_bad[2][32];

// ================= K1: mask-layout detect only =================
// int32 0/1 arrays have all bytes at idx%4!=0 equal to zero.
__global__ void k_prep(const unsigned char* __restrict__ p0,
                       const unsigned char* __restrict__ p1) {
    const int b = blockIdx.x, t = threadIdx.x;
    __shared__ int bad0, bad1;
    if (t == 0) { bad0 = 0; bad1 = 0; }
    __syncthreads();
    int idx = b*256 + t;                 // 32 blocks x 256 = 8192 = MM bytes
    if ((idx & 3) != 0) {
        if (p0[idx]) atomicOr(&bad0, 1);
        if (p1[idx]) atomicOr(&bad1, 1);
    }
    __syncthreads();
    if (t == 0) { g_bad[0][b] = bad0; g_bad[1][b] = bad1; }
}

// ================= K2: hist + cond_pool fused =================
__global__ void k_hist_cond(const int* __restrict__ dst,
                            const float* __restrict__ obj_x, const float* __restrict__ obj_pos,
                            const int* __restrict__ nuc, const void* central, const void* backbone,
                            const int* __restrict__ obatch,
                            const float* __restrict__ Wn, const float* __restrict__ bn) {
    const int t = threadIdx.x;
    if (blockIdx.x < 64) {
        const int e0 = (blockIdx.x*256 + t) * 8;
        int4 d0 = *(const int4*)(dst + e0);
        int4 d1 = *(const int4*)(dst + e0 + 4);
        atomicAdd(&g_cnt[d0.x], 1); atomicAdd(&g_cnt[d0.y], 1);
        atomicAdd(&g_cnt[d0.z], 1); atomicAdd(&g_cnt[d0.w], 1);
        atomicAdd(&g_cnt[d1.x], 1); atomicAdd(&g_cnt[d1.y], 1);
        atomicAdd(&g_cnt[d1.z], 1); atomicAdd(&g_cnt[d1.w], 1);
        return;
    }
    int f0 = __syncthreads_or(t < 32 ? g_bad[0][t] : 0);
    int f1 = __syncthreads_or(t < 32 ? g_bad[1][t] : 0);
    const int fC = !f0, fB = !f1;        // 1 => int32 layout
    if (t >= 128) return;
    const int c = t;
    const int m0 = (blockIdx.x - 64) * 32;
    float acc = 0.f, cntloc = 0.f; int cur_g = -1;
    for (int mm = 0; mm < 32; mm++) {
        int m = m0 + mm;
        int nv = nuc[m];
        bool cen = fC ? (((const int*)central)[m] != 0) : (((const unsigned char*)central)[m] != 0);
        bool bb  = fB ? (((const int*)backbone)[m] != 0) : (((const unsigned char*)backbone)[m] != 0);
        bool base = !bb;
        bool cond = (nv == 0) || (cen && base) || ((nv == 2) && base);
        if (!cond) continue;
        int g = obatch[m];
        float e = bn[c];
        #pragma unroll
        for (int k = 0; k < 13; k++) e += obj_x[m*13 + k] * Wn[k*HH + c];
        #pragma unroll
        for (int k = 0; k < 3; k++)  e += obj_pos[m*3 + k] * Wn[(13+k)*HH + c];
        if (g != cur_g) {
            if (cur_g >= 0) {
                atomicAdd(&g_condsum[cur_g*HH + c], acc);
                if (c == 0) atomicAdd(&g_condcnt[cur_g], cntloc);
            }
            cur_g = g; acc = e; cntloc = 1.f;
        } else { acc += e; cntloc += 1.f; }
    }
    if (cur_g >= 0) {
        atomicAdd(&g_condsum[cur_g*HH + c], acc);
        if (c == 0) atomicAdd(&g_condcnt[cur_g], cntloc);
    }
}

// ================= K3: scan (block 0, self-cleans g_cnt) + graph_h ===========
__global__ void k_scan_graph(const int* __restrict__ timestep,
                             const float* __restrict__ Wt, const float* __restrict__ bt,
                             const float* __restrict__ Wc, const float* __restrict__ bc) {
    if (blockIdx.x == 0) {
        __shared__ int s[1024];
        const int t = threadIdx.x;
        int v0 = g_cnt[4*t], v1 = g_cnt[4*t+1], v2 = g_cnt[4*t+2], v3 = g_cnt[4*t+3];
        g_cnt[4*t] = 0; g_cnt[4*t+1] = 0; g_cnt[4*t+2] = 0; g_cnt[4*t+3] = 0;
        g_dinv[4*t]   = rsqrtf((float)(v0 + 1));
        g_dinv[4*t+1] = rsqrtf((float)(v1 + 1));
        g_dinv[4*t+2] = rsqrtf((float)(v2 + 1));
        g_dinv[4*t+3] = rsqrtf((float)(v3 + 1));
        int sum = v0 + v1 + v2 + v3;
        s[t] = sum; __syncthreads();
        for (int off = 1; off < 1024; off <<= 1) {
            int x = (t >= off) ? s[t - off] : 0;
            __syncthreads();
            s[t] += x;
            __syncthreads();
        }
        int excl = s[t] - sum;
        g_rowptr[4*t]   = excl;
        g_rowptr[4*t+1] = excl + v0;
        g_rowptr[4*t+2] = excl + v0 + v1;
        g_rowptr[4*t+3] = excl + v0 + v1 + v2;
        if (t == 1023) g_rowptr[NN] = excl + sum;
        return;
    }
    __shared__ float te[HH], pe[HH];
    const int g = blockIdx.x - 1, c = threadIdx.x;
    if (c < HH) {
        float tv = (float)timestep[g];
        const float L = 9.210340371976184f;
        if (c < 64) te[c] = cosf(tv * expf(-L * (float)c / 64.f));
        else        te[c] = sinf(tv * expf(-L * (float)(c - 64) / 64.f));
        float cntv = g_condcnt[g];
        pe[c] = g_condsum[g*HH + c] / fmaxf(cntv, 1.0f);
        g_condsum[g*HH + c] = 0.f;      // self-clean (own element, read first)
    }
    __syncthreads();
    if (c == 0) g_condcnt[g] = 0.f;     // after barrier: all reads done
    if (c < HH) {
        float a = bt[c] + bc[c];
        #pragma unroll 8
        for (int k = 0; k < HH; k++)
            a += te[k] * Wt[k*HH + c] + pe[k] * Wc[k*HH + c];
        g_gh[g*HH + c] = a;
    }
}

// ================= K4: CSR fill + gemm1 (fused node embedding) ================
// gemm blocks: 16 rows x 128 cols, 256 threads, full W1 in dynamic smem,
// single __syncthreads, epilogue scales by dinv. dest g_buf[0].
#define SMEM1 ((HH*HH + 16*HH + 16*NDD + HH + 16) * 4)
__global__ void k_fill_gemm1(const int* __restrict__ src, const int* __restrict__ dst,
                             const float* __restrict__ W1,
                             const float* __restrict__ x, const int* __restrict__ bmap,
                             const float* __restrict__ Wn, const float* __restrict__ bn) {
    if (blockIdx.x < 64) {
        const int t = threadIdx.x;
        const int e0 = (blockIdx.x*256 + t) * 8;
        int4 s0 = *(const int4*)(src + e0);
        int4 s1 = *(const int4*)(src + e0 + 4);
        int4 d0 = *(const int4*)(dst + e0);
        int4 d1 = *(const int4*)(dst + e0 + 4);
        g_csr[atomicAdd(&g_rowptr[d0.x], 1)] = s0.x;
        g_csr[atomicAdd(&g_rowptr[d0.y], 1)] = s0.y;
        g_csr[atomicAdd(&g_rowptr[d0.z], 1)] = s0.z;
        g_csr[atomicAdd(&g_rowptr[d0.w], 1)] = s0.w;
        g_csr[atomicAdd(&g_rowptr[d1.x], 1)] = s1.x;
        g_csr[atomicAdd(&g_rowptr[d1.y], 1)] = s1.y;
        g_csr[atomicAdd(&g_rowptr[d1.z], 1)] = s1.z;
        g_csr[atomicAdd(&g_rowptr[d1.w], 1)] = s1.w;
        return;
    }
    extern __shared__ float sm[];
    float* Ws  = sm;                        // 16384
    float* As  = sm + HH*HH;                // 2048  (16 rows x 128)
    float* xr  = As + 16*HH;                // 256   (16 x 16)
    float* bns = xr + 16*NDD;               // 128
    int*   gidx = (int*)(bns + HH);         // 16

    const int blk = blockIdx.x - 64;
    const int i0 = blk * 16;
    const int t = threadIdx.x;
    const int c = t & 127, rg = t >> 7;

    // preload full W1
    {
        const float4* w4 = (const float4*)W1;
        float4* s4 = (float4*)Ws;
        #pragma unroll
        for (int j = 0; j < 16; j++) s4[t + 256*j] = w4[t + 256*j];
    }
    if (t < 128) bns[t] = bn[t];
    if (t < 16) gidx[t] = bmap[i0 + t];
    xr[t] = x[i0*NDD + t];                  // 256 floats
    __syncthreads();

    // node embedding into As (Wn read direct; hoisted per-thread column)
    {
        float wnk[NDD];
        #pragma unroll
        for (int k = 0; k < NDD; k++) wnk[k] = Wn[k*HH + c];
        #pragma unroll
        for (int r8 = 0; r8 < 8; r8++) {
            int r = rg*8 + r8;
            float a = bns[c] + g_gh[gidx[r]*HH + c];
            #pragma unroll
            for (int k = 0; k < NDD; k++) a += xr[r*NDD + k] * wnk[k];
            As[r*HH + c] = a;
        }
    }
    __syncthreads();

    float acc[8] = {0,0,0,0,0,0,0,0};
    const float4* As4 = (const float4*)As;
    #pragma unroll 8
    for (int k0 = 0; k0 < HH; k0 += 4) {
        float w0 = Ws[(k0+0)*HH + c], w1 = Ws[(k0+1)*HH + c];
        float w2 = Ws[(k0+2)*HH + c], w3 = Ws[(k0+3)*HH + c];
        int k4 = k0 >> 2;
        #pragma unroll
        for (int r = 0; r < 8; r++) {
            float4 a4 = As4[(rg*8 + r)*32 + k4];
            acc[r] += a4.x*w0 + a4.y*w1 + a4.z*w2 + a4.w*w3;
        }
    }
    #pragma unroll
    for (int r = 0; r < 8; r++) {
        int i = i0 + rg*8 + r;
        g_buf[0][i*HH + c] = g_dinv[i] * acc[r];
    }
}

// ================= K5: agg1 + gemm2 fused =================
// 512 threads: phase1 warp-per-node (16 nodes) -> h1 in smem; phase2 GEMM.
// consumed rowptr: node i range = [rp[i-1], rp[i]) (rp[-1]=0).
#define SMEM2 ((HH*HH + 16*HH) * 4)
__global__ void k_agg_gemm2(const float* __restrict__ b1, const float* __restrict__ W2) {
    extern __shared__ float sm[];
    float* Ws = sm;                 // 16384
    float* As = sm + HH*HH;         // 2048
    const int t = threadIdx.x;

    // preload full W2 (512 threads x 8 float4)
    {
        const float4* w4 = (const float4*)W2;
        float4* s4 = (float4*)Ws;
        #pragma unroll
        for (int j = 0; j < 8; j++) s4[t + 512*j] = w4[t + 512*j];
    }

    // phase 1: aggregate
    const int warp = t >> 5, lane = t & 31;
    const int i = blockIdx.x*16 + warp;
    const float4* __restrict__ xw = (const float4*)g_buf[0];
    float4 acc = xw[i*32 + lane];               // self (pre-scaled)
    const int s0 = (i == 0) ? 0 : g_rowptr[i-1];
    const int s1 = g_rowptr[i];
    int e = s0;
    for (; e + 4 <= s1; e += 4) {
        int a0 = g_csr[e], a1 = g_csr[e+1], a2 = g_csr[e+2], a3 = g_csr[e+3];
        float4 v0 = xw[a0*32 + lane], v1 = xw[a1*32 + lane];
        float4 v2 = xw[a2*32 + lane], v3 = xw[a3*32 + lane];
        acc.x += (v0.x + v1.x) + (v2.x + v3.x);
        acc.y += (v0.y + v1.y) + (v2.y + v3.y);
        acc.z += (v0.z + v1.z) + (v2.z + v3.z);
        acc.w += (v0.w + v1.w) + (v2.w + v3.w);
    }
    for (; e < s1; e++) {
        float4 v = xw[g_csr[e]*32 + lane];
        acc.x += v.x; acc.y += v.y; acc.z += v.z; acc.w += v.w;
    }
    {
        const float di = g_dinv[i];
        const float4 b4 = ((const float4*)b1)[lane];
        float4 h;
        h.x = fmaxf(di*acc.x + b4.x, 0.f);
        h.y = fmaxf(di*acc.y + b4.y, 0.f);
        h.z = fmaxf(di*acc.z + b4.z, 0.f);
        h.w = fmaxf(di*acc.w + b4.w, 0.f);
        ((float4*)(As + warp*HH))[lane] = h;
    }
    __syncthreads();

    // phase 2: GEMM 16x128 @ 128x128, 512 threads -> 4 rows/thread
    const int c = t & 127, rq = t >> 7;         // rq in 0..3
    float acc2[4] = {0,0,0,0};
    const float4* As4 = (const float4*)As;
    #pragma unroll 8
    for (int k0 = 0; k0 < HH; k0 += 4) {
        float w0 = Ws[(k0+0)*HH + c], w1 = Ws[(k0+1)*HH + c];
        float w2 = Ws[(k0+2)*HH + c], w3 = Ws[(k0+3)*HH + c];
        int k4 = k0 >> 2;
        #pragma unroll
        for (int r = 0; r < 4; r++) {
            float4 a4 = As4[(rq*4 + r)*32 + k4];
            acc2[r] += a4.x*w0 + a4.y*w1 + a4.z*w2 + a4.w*w3;
        }
    }
    const int i0 = blockIdx.x*16;
    #pragma unroll
    for (int r = 0; r < 4; r++) {
        int i2 = i0 + rq*4 + r;
        g_buf[1][i2*HH + c] = g_dinv[i2] * acc2[r];
    }
}

// ================= K6: agg2 + head fused (warp-per-node) =================
__global__ void k_agg_head(const float* __restrict__ bias,
                           const float* __restrict__ Wo, const float* __restrict__ bo,
                           const float* __restrict__ we, float* __restrict__ out_nodes) {
    const int i = (blockIdx.x * blockDim.x + threadIdx.x) >> 5;
    if (i >= NN) return;
    const int lane = threadIdx.x & 31;
    const float4* __restrict__ xw = (const float4*)g_buf[1];
    float4 acc = xw[i*32 + lane];
    const int s0 = (i == 0) ? 0 : g_rowptr[i-1];
    const int s1 = g_rowptr[i];
    int e = s0;
    for (; e + 4 <= s1; e += 4) {
        int a0 = g_csr[e], a1 = g_csr[e+1], a2 = g_csr[e+2], a3 = g_csr[e+3];
        float4 v0 = xw[a0*32 + lane], v1 = xw[a1*32 + lane];
        float4 v2 = xw[a2*32 + lane], v3 = xw[a3*32 + lane];
        acc.x += (v0.x + v1.x) + (v2.x + v3.x);
        acc.y += (v0.y + v1.y) + (v2.y + v3.y);
        acc.z += (v0.z + v1.z) + (v2.z + v3.z);
        acc.w += (v0.w + v1.w) + (v2.w + v3.w);
    }
    for (; e < s1; e++) {
        float4 v = xw[g_csr[e]*32 + lane];
        acc.x += v.x; acc.y += v.y; acc.z += v.z; acc.w += v.w;
    }
    const float di = g_dinv[i];
    const float4 b4 = ((const float4*)bias)[lane];
    float4 h;
    h.x = fmaxf(di*acc.x + b4.x, 0.f);
    h.y = fmaxf(di*acc.y + b4.y, 0.f);
    h.z = fmaxf(di*acc.z + b4.z, 0.f);
    h.w = fmaxf(di*acc.w + b4.w, 0.f);

    const float4 wl4 = ((const float4*)we)[lane];
    const float4 wr4 = ((const float4*)we)[32 + lane];
    float pl = h.x*wl4.x + h.y*wl4.y + h.z*wl4.z + h.w*wl4.w;
    float pr = h.x*wr4.x + h.y*wr4.y + h.z*wr4.z + h.w*wr4.w;

    float p[NDD];
    #pragma unroll
    for (int c = 0; c < NDD; c++) p[c] = 0.f;
    const float4* Wo4 = (const float4*)Wo;
    float hv[4] = {h.x, h.y, h.z, h.w};
    #pragma unroll
    for (int j = 0; j < 4; j++) {
        int k = lane*4 + j;
        #pragma unroll
        for (int c4 = 0; c4 < 4; c4++) {
            float4 w = Wo4[k*4 + c4];
            p[c4*4+0] += hv[j]*w.x; p[c4*4+1] += hv[j]*w.y;
            p[c4*4+2] += hv[j]*w.z; p[c4*4+3] += hv[j]*w.w;
        }
    }
    #pragma unroll
    for (int off = 16; off > 0; off >>= 1) {
        pl += __shfl_down_sync(0xffffffffu, pl, off);
        pr += __shfl_down_sync(0xffffffffu, pr, off);
        #pragma unroll
        for (int c = 0; c < NDD; c++)
            p[c] += __shfl_down_sync(0xffffffffu, p[c], off);
    }
    if (lane == 0) {
        g_sl[i] = pl;
        g_sr[i] = pr;
        float4* on4 = (float4*)(out_nodes + i*NDD);
        const float4* bo4 = (const float4*)bo;
        #pragma unroll
        for (int c4 = 0; c4 < 4; c4++) {
            float4 b = bo4[c4];
            float4 v;
            v.x = p[c4*4+0] + b.x; v.y = p[c4*4+1] + b.y;
            v.z = p[c4*4+2] + b.z; v.w = p[c4*4+3] + b.w;
            on4[c4] = v;
        }
    }
}

// ================= K7: edges (row-pair balanced, float4 stores) ===============
__global__ void k_edges(const float* __restrict__ bedge, float* __restrict__ out_edges) {
    const float be = bedge[0];
    const int bi = blockIdx.x;
    const int t = threadIdx.x;
    #pragma unroll
    for (int half = 0; half < 2; half++) {
        const int i = (half == 0) ? bi : (NN - 2 - bi);
        if (half == 1 && i <= bi) break;
        const int cnt = NN - 1 - i;
        const long long off = (long long)i * (2LL*NN - i - 1) / 2;
        const float sl = g_sl[i] + be;
        float* o = out_edges + off;
        const float* sr = g_sr + i + 1;
        const int pre0 = (int)((4 - (off & 3)) & 3);
        const int pre = pre0 < cnt ? pre0 : cnt;
        if (t < pre) o[t] = sl + sr[t];
        const int nv = (cnt - pre) >> 2;
        float4* o4 = (float4*)(o + pre);
        for (int v = t; v < nv; v += 256) {
            int j = pre + v*4;
            float4 r;
            r.x = sl + sr[j];   r.y = sl + sr[j+1];
            r.z = sl + sr[j+2]; r.w = sl + sr[j+3];
            o4[v] = r;
        }
        const int tail0 = pre + nv*4;
        const int rem = cnt - tail0;
        if (t < rem) o[tail0 + t] = sl + sr[tail0 + t];
    }
}

// ================= launch =================
extern "C" void kernel_launch(void* const* d_in, const int* in_sizes, int n_in,
                              void* d_out, int out_size) {
    const float* x        = (const float*)d_in[0];
    const int*   eidx     = (const int*)d_in[1];
    const int*   timestep = (const int*)d_in[2];
    const int*   bmap     = (const int*)d_in[3];
    const int*   nuc      = (const int*)d_in[4];
    const void*  central  = d_in[5];
    const void*  backbone = d_in[6];
    const float* obj_x    = (const float*)d_in[7];
    const float* obj_pos  = (const float*)d_in[8];
    const int*   obatch   = (const int*)d_in[9];
    const float* Wn = (const float*)d_in[10]; const float* bn = (const float*)d_in[11];
    const float* Wc = (const float*)d_in[12]; const float* bc = (const float*)d_in[13];
    const float* Wt = (const float*)d_in[14]; const float* bt = (const float*)d_in[15];
    const float* W1 = (const float*)d_in[16]; const float* b1 = (const float*)d_in[17];
    const float* W2 = (const float*)d_in[18]; const float* b2 = (const float*)d_in[19];
    const float* Wo = (const float*)d_in[20]; const float* bo = (const float*)d_in[21];
    const float* we = (const float*)d_in[22]; const float* be = (const float*)d_in[23];

    float* out = (float*)d_out;
    float* out_nodes = out;
    float* out_edges = out + NN*NDD;

    const int* esrc = eidx;
    const int* edst = eidx + EE;

    cudaFuncSetAttribute(k_fill_gemm1, cudaFuncAttributeMaxDynamicSharedMemorySize, SMEM1);
    cudaFuncSetAttribute(k_agg_gemm2,  cudaFuncAttributeMaxDynamicSharedMemorySize, SMEM2);

    k_prep<<<32, 256>>>((const unsigned char*)central, (const unsigned char*)backbone);
    k_hist_cond<<<320, 256>>>(edst, obj_x, obj_pos, nuc, central, backbone, obatch, Wn, bn);
    k_scan_graph<<<9, 1024>>>(timestep, Wt, bt, Wc, bc);
    k_fill_gemm1<<<64 + NN/16, 256, SMEM1>>>(esrc, edst, W1, x, bmap, Wn, bn);
    k_agg_gemm2<<<NN/16, 512, SMEM2>>>(b1, W2);
    k_agg_head<<<NN/8, 256>>>(b2, Wo, bo, we, out_nodes);
    k_edges<<<NN/2, 256>>>(be, out_edges);
}

// round 8
// speedup vs baseline: 1.3479x; 1.0806x over previous
#include <cuda_runtime.h>
#include <math.h>

#define NN 4096
#define MM 8192
#define GG 8
#define HH 128
#define NDD 16
#define EE 131072
#define WSP 132   // padded smem row stride (floats)

// ---------------- device scratch ----------------
__device__ float g_buf[2][NN*HH];   // 0: xw1, 1: xw2
__device__ int   g_cnt[NN];
__device__ int   g_rowptr[NN+1];    // doubles as fill cursor (consumed semantics)
__device__ int   g_csr[EE];
__device__ float g_dinv[NN];
__device__ float g_condsum[GG*HH];
__device__ float g_condcnt[GG];
__device__ float g_gh[GG*HH];
__device__ float g_sl[NN];
__device__ float g_sr[NN];
__device__ int   g_bad[2][32];

// ---------------- tf32 helpers ----------------
__device__ __forceinline__ void mma_tf32(float c[4],
        unsigned a0, unsigned a1, unsigned a2, unsigned a3,
        unsigned b0, unsigned b1) {
    asm volatile(
        "mma.sync.aligned.m16n8k8.row.col.f32.tf32.tf32.f32 "
        "{%0,%1,%2,%3}, {%4,%5,%6,%7}, {%8,%9}, {%0,%1,%2,%3};"
        : "+f"(c[0]), "+f"(c[1]), "+f"(c[2]), "+f"(c[3])
        : "r"(a0), "r"(a1), "r"(a2), "r"(a3), "r"(b0), "r"(b1));
}
__device__ __forceinline__ unsigned tf32_rna(float v) {
    unsigned r; asm("cvt.rna.tf32.f32 %0, %1;" : "=r"(r) : "f"(v)); return r;
}
// split v into hi (tf32) + lo (tf32 of residual)
__device__ __forceinline__ void tf32_split(float v, unsigned& hi, unsigned& lo) {
    hi = tf32_rna(v);
    lo = tf32_rna(v - __uint_as_float(hi));
}

// ================= K1: mask-layout detect =================
__global__ void k_prep(const unsigned char* __restrict__ p0,
                       const unsigned char* __restrict__ p1) {
    const int b = blockIdx.x, t = threadIdx.x;
    __shared__ int bad0, bad1;
    if (t == 0) { bad0 = 0; bad1 = 0; }
    __syncthreads();
    int idx = b*256 + t;
    if ((idx & 3) != 0) {
        if (p0[idx]) atomicOr(&bad0, 1);
        if (p1[idx]) atomicOr(&bad1, 1);
    }
    __syncthreads();
    if (t == 0) { g_bad[0][b] = bad0; g_bad[1][b] = bad1; }
}

// ================= K2: hist + cond_pool fused =================
__global__ void k_hist_cond(const int* __restrict__ dst,
                            const float* __restrict__ obj_x, const float* __restrict__ obj_pos,
                            const int* __restrict__ nuc, const void* central, const void* backbone,
                            const int* __restrict__ obatch,
                            const float* __restrict__ Wn, const float* __restrict__ bn) {
    const int t = threadIdx.x;
    if (blockIdx.x < 128) {
        const int e0 = (blockIdx.x*256 + t) * 4;
        int4 d0 = *(const int4*)(dst + e0);
        atomicAdd(&g_cnt[d0.x], 1); atomicAdd(&g_cnt[d0.y], 1);
        atomicAdd(&g_cnt[d0.z], 1); atomicAdd(&g_cnt[d0.w], 1);
        return;
    }
    int f0 = __syncthreads_or(t < 32 ? g_bad[0][t] : 0);
    int f1 = __syncthreads_or(t < 32 ? g_bad[1][t] : 0);
    const int fC = !f0, fB = !f1;
    if (t >= 128) return;
    const int c = t;
    const int m0 = (blockIdx.x - 128) * 32;
    float acc = 0.f, cntloc = 0.f; int cur_g = -1;
    for (int mm = 0; mm < 32; mm++) {
        int m = m0 + mm;
        int nv = nuc[m];
        bool cen = fC ? (((const int*)central)[m] != 0) : (((const unsigned char*)central)[m] != 0);
        bool bb  = fB ? (((const int*)backbone)[m] != 0) : (((const unsigned char*)backbone)[m] != 0);
        bool base = !bb;
        bool cond = (nv == 0) || (cen && base) || ((nv == 2) && base);
        if (!cond) continue;
        int g = obatch[m];
        float e = bn[c];
        #pragma unroll
        for (int k = 0; k < 13; k++) e += obj_x[m*13 + k] * Wn[k*HH + c];
        #pragma unroll
        for (int k = 0; k < 3; k++)  e += obj_pos[m*3 + k] * Wn[(13+k)*HH + c];
        if (g != cur_g) {
            if (cur_g >= 0) {
                atomicAdd(&g_condsum[cur_g*HH + c], acc);
                if (c == 0) atomicAdd(&g_condcnt[cur_g], cntloc);
            }
            cur_g = g; acc = e; cntloc = 1.f;
        } else { acc += e; cntloc += 1.f; }
    }
    if (cur_g >= 0) {
        atomicAdd(&g_condsum[cur_g*HH + c], acc);
        if (c == 0) atomicAdd(&g_condcnt[cur_g], cntloc);
    }
}

// ================= K3: scan (block 0, self-cleans g_cnt) + graph_h ===========
__global__ void k_scan_graph(const int* __restrict__ timestep,
                             const float* __restrict__ Wt, const float* __restrict__ bt,
                             const float* __restrict__ Wc, const float* __restrict__ bc) {
    if (blockIdx.x == 0) {
        __shared__ int s[1024];
        const int t = threadIdx.x;
        int v0 = g_cnt[4*t], v1 = g_cnt[4*t+1], v2 = g_cnt[4*t+2], v3 = g_cnt[4*t+3];
        g_cnt[4*t] = 0; g_cnt[4*t+1] = 0; g_cnt[4*t+2] = 0; g_cnt[4*t+3] = 0;
        g_dinv[4*t]   = rsqrtf((float)(v0 + 1));
        g_dinv[4*t+1] = rsqrtf((float)(v1 + 1));
        g_dinv[4*t+2] = rsqrtf((float)(v2 + 1));
        g_dinv[4*t+3] = rsqrtf((float)(v3 + 1));
        int sum = v0 + v1 + v2 + v3;
        s[t] = sum; __syncthreads();
        for (int off = 1; off < 1024; off <<= 1) {
            int x = (t >= off) ? s[t - off] : 0;
            __syncthreads();
            s[t] += x;
            __syncthreads();
        }
        int excl = s[t] - sum;
        g_rowptr[4*t]   = excl;
        g_rowptr[4*t+1] = excl + v0;
        g_rowptr[4*t+2] = excl + v0 + v1;
        g_rowptr[4*t+3] = excl + v0 + v1 + v2;
        if (t == 1023) g_rowptr[NN] = excl + sum;
        return;
    }
    __shared__ float te[HH], pe[HH];
    const int g = blockIdx.x - 1, c = threadIdx.x;
    if (c < HH) {
        float tv = (float)timestep[g];
        const float L = 9.210340371976184f;
        if (c < 64) te[c] = cosf(tv * expf(-L * (float)c / 64.f));
        else        te[c] = sinf(tv * expf(-L * (float)(c - 64) / 64.f));
        float cntv = g_condcnt[g];
        pe[c] = g_condsum[g*HH + c] / fmaxf(cntv, 1.0f);
        g_condsum[g*HH + c] = 0.f;
    }
    __syncthreads();
    if (c == 0) g_condcnt[g] = 0.f;
    if (c < HH) {
        float a = bt[c] + bc[c];
        #pragma unroll 8
        for (int k = 0; k < HH; k++)
            a += te[k] * Wt[k*HH + c] + pe[k] * Wc[k*HH + c];
        g_gh[g*HH + c] = a;
    }
}

// ================= K4: CSR fill + gemm1 (split-tf32 mma, fused node emb) ======
#define SMEM1 ((HH*WSP + 16*WSP + 16*NDD + HH + 16) * 4)
__global__ void k_fill_gemm1(const int* __restrict__ src, const int* __restrict__ dst,
                             const float* __restrict__ W1,
                             const float* __restrict__ x, const int* __restrict__ bmap,
                             const float* __restrict__ Wn, const float* __restrict__ bn) {
    if (blockIdx.x < 64) {
        const int t = threadIdx.x;
        const int e0 = (blockIdx.x*256 + t) * 8;
        int4 s0 = *(const int4*)(src + e0);
        int4 s1 = *(const int4*)(src + e0 + 4);
        int4 d0 = *(const int4*)(dst + e0);
        int4 d1 = *(const int4*)(dst + e0 + 4);
        g_csr[atomicAdd(&g_rowptr[d0.x], 1)] = s0.x;
        g_csr[atomicAdd(&g_rowptr[d0.y], 1)] = s0.y;
        g_csr[atomicAdd(&g_rowptr[d0.z], 1)] = s0.z;
        g_csr[atomicAdd(&g_rowptr[d0.w], 1)] = s0.w;
        g_csr[atomicAdd(&g_rowptr[d1.x], 1)] = s1.x;
        g_csr[atomicAdd(&g_rowptr[d1.y], 1)] = s1.y;
        g_csr[atomicAdd(&g_rowptr[d1.z], 1)] = s1.z;
        g_csr[atomicAdd(&g_rowptr[d1.w], 1)] = s1.w;
        return;
    }
    extern __shared__ float sm[];
    float* Ws  = sm;                        // 128 x 132 (k-major, padded)
    float* As  = sm + HH*WSP;               // 16 x 132
    float* xr  = As + 16*WSP;               // 16 x 16
    float* bns = xr + 16*NDD;               // 128
    int*   gidx = (int*)(bns + HH);         // 16

    const int blk = blockIdx.x - 64;
    const int i0 = blk * 16;
    const int t = threadIdx.x;
    const int lane = t & 31, wk = t >> 5;   // warp id 0..7

    // stage W1 into smem
    #pragma unroll
    for (int kt = 0; kt < 16; kt++) {
        int k = kt*8 + wk;
        float4 v = ((const float4*)(W1 + k*HH))[lane];
        *(float4*)(Ws + k*WSP + lane*4) = v;
    }
    if (t < 128) bns[t] = bn[t];
    if (t < 16) gidx[t] = bmap[i0 + t];
    xr[t] = x[i0*NDD + t];
    __syncthreads();

    // node embedding into As
    {
        const int c = t & 127, rg = t >> 7;
        float wnk[NDD];
        #pragma unroll
        for (int k = 0; k < NDD; k++) wnk[k] = Wn[k*HH + c];
        #pragma unroll
        for (int r8 = 0; r8 < 8; r8++) {
            int r = rg*8 + r8;
            float a = bns[c] + g_gh[gidx[r]*HH + c];
            #pragma unroll
            for (int k = 0; k < NDD; k++) a += xr[r*NDD + k] * wnk[k];
            As[r*WSP + c] = a;
        }
    }
    __syncthreads();

    // split-tf32 mma: warp wk computes 16 rows x 16 cols at n0 = wk*16
    const int g = lane >> 2, tig = lane & 3;
    const int n0 = wk * 16;
    float c0[4] = {0,0,0,0}, c1[4] = {0,0,0,0};
    const float* A0 = As + g*WSP;
    const float* A1 = As + (g+8)*WSP;
    #pragma unroll
    for (int kt = 0; kt < 16; kt++) {
        int k0 = kt*8;
        unsigned ah0,al0, ah1,al1, ah2,al2, ah3,al3;
        tf32_split(A0[k0+tig],   ah0, al0);
        tf32_split(A1[k0+tig],   ah1, al1);
        tf32_split(A0[k0+tig+4], ah2, al2);
        tf32_split(A1[k0+tig+4], ah3, al3);
        const float* B0 = Ws + (k0+tig)*WSP;
        const float* B1 = Ws + (k0+tig+4)*WSP;
        unsigned bh0,bl0, bh1,bl1, bh2,bl2, bh3,bl3;
        tf32_split(B0[n0+g],   bh0, bl0);
        tf32_split(B1[n0+g],   bh1, bl1);
        tf32_split(B0[n0+8+g], bh2, bl2);
        tf32_split(B1[n0+8+g], bh3, bl3);
        mma_tf32(c0, ah0,ah1,ah2,ah3, bh0,bh1);
        mma_tf32(c0, ah0,ah1,ah2,ah3, bl0,bl1);
        mma_tf32(c0, al0,al1,al2,al3, bh0,bh1);
        mma_tf32(c1, ah0,ah1,ah2,ah3, bh2,bh3);
        mma_tf32(c1, ah0,ah1,ah2,ah3, bl2,bl3);
        mma_tf32(c1, al0,al1,al2,al3, bh2,bh3);
    }
    const int r0 = i0 + g, r1 = i0 + g + 8;
    const float d0 = g_dinv[r0], d1 = g_dinv[r1];
    *(float2*)&g_buf[0][r0*HH + n0 + 2*tig]     = make_float2(d0*c0[0], d0*c0[1]);
    *(float2*)&g_buf[0][r0*HH + n0 + 8 + 2*tig] = make_float2(d0*c1[0], d0*c1[1]);
    *(float2*)&g_buf[0][r1*HH + n0 + 2*tig]     = make_float2(d1*c0[2], d1*c0[3]);
    *(float2*)&g_buf[0][r1*HH + n0 + 8 + 2*tig] = make_float2(d1*c1[2], d1*c1[3]);
}

// ================= K5: agg1 + gemm2 fused (split-tf32 mma phase 2) ============
#define SMEM2 ((HH*WSP + 16*WSP) * 4)
__global__ void k_agg_gemm2(const float* __restrict__ b1, const float* __restrict__ W2) {
    extern __shared__ float sm[];
    float* Ws = sm;                 // 128 x 132
    float* As = sm + HH*WSP;        // 16 x 132
    const int t = threadIdx.x;
    const int lane = t & 31, warp = t >> 5;   // warp 0..15

    // stage W2
    #pragma unroll
    for (int kt = 0; kt < 8; kt++) {
        int k = kt*16 + warp;
        float4 v = ((const float4*)(W2 + k*HH))[lane];
        *(float4*)(Ws + k*WSP + lane*4) = v;
    }

    // phase 1: warp-per-node aggregate
    const int i = blockIdx.x*16 + warp;
    const float4* __restrict__ xw = (const float4*)g_buf[0];
    float4 acc = xw[i*32 + lane];
    const int s0 = (i == 0) ? 0 : g_rowptr[i-1];
    const int s1 = g_rowptr[i];
    int e = s0;
    for (; e + 4 <= s1; e += 4) {
        int a0 = g_csr[e], a1 = g_csr[e+1], a2 = g_csr[e+2], a3 = g_csr[e+3];
        float4 v0 = xw[a0*32 + lane], v1 = xw[a1*32 + lane];
        float4 v2 = xw[a2*32 + lane], v3 = xw[a3*32 + lane];
        acc.x += (v0.x + v1.x) + (v2.x + v3.x);
        acc.y += (v0.y + v1.y) + (v2.y + v3.y);
        acc.z += (v0.z + v1.z) + (v2.z + v3.z);
        acc.w += (v0.w + v1.w) + (v2.w + v3.w);
    }
    for (; e < s1; e++) {
        float4 v = xw[g_csr[e]*32 + lane];
        acc.x += v.x; acc.y += v.y; acc.z += v.z; acc.w += v.w;
    }
    {
        const float di = g_dinv[i];
        const float4 b4 = ((const float4*)b1)[lane];
        float4 h;
        h.x = fmaxf(di*acc.x + b4.x, 0.f);
        h.y = fmaxf(di*acc.y + b4.y, 0.f);
        h.z = fmaxf(di*acc.z + b4.z, 0.f);
        h.w = fmaxf(di*acc.w + b4.w, 0.f);
        ((float4*)(As + warp*WSP))[lane] = h;
    }
    __syncthreads();

    // phase 2: split-tf32 mma, warp -> m16 n8 tile at n0 = warp*8
    const int g = lane >> 2, tig = lane & 3;
    const int n0 = warp * 8;
    float c0[4] = {0,0,0,0};
    const float* A0 = As + g*WSP;
    const float* A1 = As + (g+8)*WSP;
    #pragma unroll
    for (int kt = 0; kt < 16; kt++) {
        int k0 = kt*8;
        unsigned ah0,al0, ah1,al1, ah2,al2, ah3,al3;
        tf32_split(A0[k0+tig],   ah0, al0);
        tf32_split(A1[k0+tig],   ah1, al1);
        tf32_split(A0[k0+tig+4], ah2, al2);
        tf32_split(A1[k0+tig+4], ah3, al3);
        const float* B0 = Ws + (k0+tig)*WSP;
        const float* B1 = Ws + (k0+tig+4)*WSP;
        unsigned bh0,bl0, bh1,bl1;
        tf32_split(B0[n0+g], bh0, bl0);
        tf32_split(B1[n0+g], bh1, bl1);
        mma_tf32(c0, ah0,ah1,ah2,ah3, bh0,bh1);
        mma_tf32(c0, ah0,ah1,ah2,ah3, bl0,bl1);
        mma_tf32(c0, al0,al1,al2,al3, bh0,bh1);
    }
    const int i0 = blockIdx.x*16;
    const int r0 = i0 + g, r1 = i0 + g + 8;
    const float d0 = g_dinv[r0], d1 = g_dinv[r1];
    *(float2*)&g_buf[1][r0*HH + n0 + 2*tig] = make_float2(d0*c0[0], d0*c0[1]);
    *(float2*)&g_buf[1][r1*HH + n0 + 2*tig] = make_float2(d1*c0[2], d1*c0[3]);
}

// ================= K6: agg2 + head fused (warp-per-node) =================
__global__ void k_agg_head(const float* __restrict__ bias,
                           const float* __restrict__ Wo, const float* __restrict__ bo,
                           const float* __restrict__ we, float* __restrict__ out_nodes) {
    const int i = (blockIdx.x * blockDim.x + threadIdx.x) >> 5;
    if (i >= NN) return;
    const int lane = threadIdx.x & 31;
    const float4* __restrict__ xw = (const float4*)g_buf[1];
    float4 acc = xw[i*32 + lane];
    const int s0 = (i == 0) ? 0 : g_rowptr[i-1];
    const int s1 = g_rowptr[i];
    int e = s0;
    for (; e + 4 <= s1; e += 4) {
        int a0 = g_csr[e], a1 = g_csr[e+1], a2 = g_csr[e+2], a3 = g_csr[e+3];
        float4 v0 = xw[a0*32 + lane], v1 = xw[a1*32 + lane];
        float4 v2 = xw[a2*32 + lane], v3 = xw[a3*32 + lane];
        acc.x += (v0.x + v1.x) + (v2.x + v3.x);
        acc.y += (v0.y + v1.y) + (v2.y + v3.y);
        acc.z += (v0.z + v1.z) + (v2.z + v3.z);
        acc.w += (v0.w + v1.w) + (v2.w + v3.w);
    }
    for (; e < s1; e++) {
        float4 v = xw[g_csr[e]*32 + lane];
        acc.x += v.x; acc.y += v.y; acc.z += v.z; acc.w += v.w;
    }
    const float di = g_dinv[i];
    const float4 b4 = ((const float4*)bias)[lane];
    float4 h;
    h.x = fmaxf(di*acc.x + b4.x, 0.f);
    h.y = fmaxf(di*acc.y + b4.y, 0.f);
    h.z = fmaxf(di*acc.z + b4.z, 0.f);
    h.w = fmaxf(di*acc.w + b4.w, 0.f);

    const float4 wl4 = ((const float4*)we)[lane];
    const float4 wr4 = ((const float4*)we)[32 + lane];
    float pl = h.x*wl4.x + h.y*wl4.y + h.z*wl4.z + h.w*wl4.w;
    float pr = h.x*wr4.x + h.y*wr4.y + h.z*wr4.z + h.w*wr4.w;

    float p[NDD];
    #pragma unroll
    for (int c = 0; c < NDD; c++) p[c] = 0.f;
    const float4* Wo4 = (const float4*)Wo;
    float hv[4] = {h.x, h.y, h.z, h.w};
    #pragma unroll
    for (int j = 0; j < 4; j++) {
        int k = lane*4 + j;
        #pragma unroll
        for (int c4 = 0; c4 < 4; c4++) {
            float4 w = Wo4[k*4 + c4];
            p[c4*4+0] += hv[j]*w.x; p[c4*4+1] += hv[j]*w.y;
            p[c4*4+2] += hv[j]*w.z; p[c4*4+3] += hv[j]*w.w;
        }
    }
    #pragma unroll
    for (int off = 16; off > 0; off >>= 1) {
        pl += __shfl_down_sync(0xffffffffu, pl, off);
        pr += __shfl_down_sync(0xffffffffu, pr, off);
        #pragma unroll
        for (int c = 0; c < NDD; c++)
            p[c] += __shfl_down_sync(0xffffffffu, p[c], off);
    }
    if (lane == 0) {
        g_sl[i] = pl;
        g_sr[i] = pr;
        float4* on4 = (float4*)(out_nodes + i*NDD);
        const float4* bo4 = (const float4*)bo;
        #pragma unroll
        for (int c4 = 0; c4 < 4; c4++) {
            float4 b = bo4[c4];
            float4 v;
            v.x = p[c4*4+0] + b.x; v.y = p[c4*4+1] + b.y;
            v.z = p[c4*4+2] + b.z; v.w = p[c4*4+3] + b.w;
            on4[c4] = v;
        }
    }
}

// ================= K7: edges (row-pair balanced, float4 stores) ===============
__global__ void k_edges(const float* __restrict__ bedge, float* __restrict__ out_edges) {
    const float be = bedge[0];
    const int bi = blockIdx.x;
    const int t = threadIdx.x;
    #pragma unroll
    for (int half = 0; half < 2; half++) {
        const int i = (half == 0) ? bi : (NN - 2 - bi);
        if (half == 1 && i <= bi) break;
        const int cnt = NN - 1 - i;
        const long long off = (long long)i * (2LL*NN - i - 1) / 2;
        const float sl = g_sl[i] + be;
        float* o = out_edges + off;
        const float* sr = g_sr + i + 1;
        const int pre0 = (int)((4 - (off & 3)) & 3);
        const int pre = pre0 < cnt ? pre0 : cnt;
        if (t < pre) o[t] = sl + sr[t];
        const int nv = (cnt - pre) >> 2;
        float4* o4 = (float4*)(o + pre);
        for (int v = t; v < nv; v += 256) {
            int j = pre + v*4;
            float4 r;
            r.x = sl + sr[j];   r.y = sl + sr[j+1];
            r.z = sl + sr[j+2]; r.w = sl + sr[j+3];
            o4[v] = r;
        }
        const int tail0 = pre + nv*4;
        const int rem = cnt - tail0;
        if (t < rem) o[tail0 + t] = sl + sr[tail0 + t];
    }
}

// ================= launch =================
extern "C" void kernel_launch(void* const* d_in, const int* in_sizes, int n_in,
                              void* d_out, int out_size) {
    const float* x        = (const float*)d_in[0];
    const int*   eidx     = (const int*)d_in[1];
    const int*   timestep = (const int*)d_in[2];
    const int*   bmap     = (const int*)d_in[3];
    const int*   nuc      = (const int*)d_in[4];
    const void*  central  = d_in[5];
    const void*  backbone = d_in[6];
    const float* obj_x    = (const float*)d_in[7];
    const float* obj_pos  = (const float*)d_in[8];
    const int*   obatch   = (const int*)d_in[9];
    const float* Wn = (const float*)d_in[10]; const float* bn = (const float*)d_in[11];
    const float* Wc = (const float*)d_in[12]; const float* bc = (const float*)d_in[13];
    const float* Wt = (const float*)d_in[14]; const float* bt = (const float*)d_in[15];
    const float* W1 = (const float*)d_in[16]; const float* b1 = (const float*)d_in[17];
    const float* W2 = (const float*)d_in[18]; const float* b2 = (const float*)d_in[19];
    const float* Wo = (const float*)d_in[20]; const float* bo = (const float*)d_in[21];
    const float* we = (const float*)d_in[22]; const float* be = (const float*)d_in[23];

    float* out = (float*)d_out;
    float* out_nodes = out;
    float* out_edges = out + NN*NDD;

    const int* esrc = eidx;
    const int* edst = eidx + EE;

    cudaFuncSetAttribute(k_fill_gemm1, cudaFuncAttributeMaxDynamicSharedMemorySize, SMEM1);
    cudaFuncSetAttribute(k_agg_gemm2,  cudaFuncAttributeMaxDynamicSharedMemorySize, SMEM2);

    k_prep<<<32, 256>>>((const unsigned char*)central, (const unsigned char*)backbone);
    k_hist_cond<<<384, 256>>>(edst, obj_x, obj_pos, nuc, central, backbone, obatch, Wn, bn);
    k_scan_graph<<<9, 1024>>>(timestep, Wt, bt, Wc, bc);
    k_fill_gemm1<<<64 + NN/16, 256, SMEM1>>>(esrc, edst, W1, x, bmap, Wn, bn);
    k_agg_gemm2<<<NN/16, 512, SMEM2>>>(b1, W2);
    k_agg_head<<<NN/8, 256>>>(b2, Wo, bo, we, out_nodes);
    k_edges<<<NN/2, 256>>>(be, out_edges);
}

// round 10
// speedup vs baseline: 1.5577x; 1.1557x over previous
#include <cuda_runtime.h>
#include <math.h>

#define NN 4096
#define MM 8192
#define GG 8
#define HH 128
#define NDD 16
#define EE 131072
#define WSP 132   // padded smem row stride (floats)

// ---------------- device scratch ----------------
__device__ float g_buf[2][NN*HH];   // 0: xw1, 1: xw2
__device__ int   g_cnt[NN];
__device__ int   g_rowptr[NN+1];    // doubles as fill cursor (consumed semantics)
__device__ int   g_csr[EE];
__device__ float g_dinv[NN];
__device__ float g_condsum[GG*HH];
__device__ float g_condcnt[GG];
__device__ float g_gh[GG*HH];
__device__ float g_sl[NN];
__device__ float g_sr[NN];
__device__ int   g_bad[2][32];

// ---------------- tf32 helpers ----------------
// HW mma.tf32 ignores the low 13 mantissa bits of the fp32 register, so the
// effective hi operand of raw v is v&0xFFFFE000; lo = v - hi is exact.
__device__ __forceinline__ void mma_tf32(float c[4],
        unsigned a0, unsigned a1, unsigned a2, unsigned a3,
        unsigned b0, unsigned b1) {
    asm volatile(
        "mma.sync.aligned.m16n8k8.row.col.f32.tf32.tf32.f32 "
        "{%0,%1,%2,%3}, {%4,%5,%6,%7}, {%8,%9}, {%0,%1,%2,%3};"
        : "+f"(c[0]), "+f"(c[1]), "+f"(c[2]), "+f"(c[3])
        : "r"(a0), "r"(a1), "r"(a2), "r"(a3), "r"(b0), "r"(b1));
}
__device__ __forceinline__ unsigned hi_of(float v) {
    return __float_as_uint(v) & 0xFFFFE000u;
}
__device__ __forceinline__ unsigned lo_of(float v, unsigned h) {
    return __float_as_uint(v - __uint_as_float(h));
}

// ================= K1: mask-layout detect =================
__global__ void k_prep(const unsigned char* __restrict__ p0,
                       const unsigned char* __restrict__ p1) {
    const int b = blockIdx.x, t = threadIdx.x;
    __shared__ int bad0, bad1;
    if (t == 0) { bad0 = 0; bad1 = 0; }
    __syncthreads();
    int idx = b*256 + t;
    if ((idx & 3) != 0) {
        if (p0[idx]) atomicOr(&bad0, 1);
        if (p1[idx]) atomicOr(&bad1, 1);
    }
    __syncthreads();
    if (t == 0) { g_bad[0][b] = bad0; g_bad[1][b] = bad1; }
}

// ================= K2: hist + cond_pool (smem-staged) =================
__global__ void k_hist_cond(const int* __restrict__ dst,
                            const float* __restrict__ obj_x, const float* __restrict__ obj_pos,
                            const int* __restrict__ nuc, const void* central, const void* backbone,
                            const int* __restrict__ obatch,
                            const float* __restrict__ Wn, const float* __restrict__ bn) {
    const int t = threadIdx.x;
    if (blockIdx.x < 128) {
        const int e0 = (blockIdx.x*256 + t) * 4;
        int4 d0 = *(const int4*)(dst + e0);
        atomicAdd(&g_cnt[d0.x], 1); atomicAdd(&g_cnt[d0.y], 1);
        atomicAdd(&g_cnt[d0.z], 1); atomicAdd(&g_cnt[d0.w], 1);
        return;
    }
    __shared__ float sox[32*13];
    __shared__ float sop[32*3];
    __shared__ int   sob[32];
    __shared__ int   scond[32];
    int f0 = __syncthreads_or(t < 32 ? g_bad[0][t] : 0);
    int f1 = __syncthreads_or(t < 32 ? g_bad[1][t] : 0);
    const int fC = !f0, fB = !f1;            // 1 => int32 layout
    const int m0 = (blockIdx.x - 128) * 32;
    for (int j = t; j < 32*13; j += 256) sox[j] = obj_x[m0*13 + j];
    for (int j = t; j < 32*3;  j += 256) sop[j] = obj_pos[m0*3 + j];
    if (t < 32) {
        int m = m0 + t;
        int nv = nuc[m];
        bool cen = fC ? (((const int*)central)[m] != 0) : (((const unsigned char*)central)[m] != 0);
        bool bb  = fB ? (((const int*)backbone)[m] != 0) : (((const unsigned char*)backbone)[m] != 0);
        bool base = !bb;
        scond[t] = (nv == 0) || (cen && base) || ((nv == 2) && base);
        sob[t] = obatch[m];
    }
    __syncthreads();
    if (t >= 128) return;
    const int c = t;
    float wnk[NDD];
    #pragma unroll
    for (int k = 0; k < NDD; k++) wnk[k] = Wn[k*HH + c];
    const float bnc = bn[c];
    float acc = 0.f, cntloc = 0.f; int cur_g = -1;
    for (int mm = 0; mm < 32; mm++) {
        if (!scond[mm]) continue;
        int g = sob[mm];
        float e = bnc;
        #pragma unroll
        for (int k = 0; k < 13; k++) e += sox[mm*13 + k] * wnk[k];
        #pragma unroll
        for (int k = 0; k < 3; k++)  e += sop[mm*3 + k] * wnk[13 + k];
        if (g != cur_g) {
            if (cur_g >= 0) {
                atomicAdd(&g_condsum[cur_g*HH + c], acc);
                if (c == 0) atomicAdd(&g_condcnt[cur_g], cntloc);
            }
            cur_g = g; acc = e; cntloc = 1.f;
        } else { acc += e; cntloc += 1.f; }
    }
    if (cur_g >= 0) {
        atomicAdd(&g_condsum[cur_g*HH + c], acc);
        if (c == 0) atomicAdd(&g_condcnt[cur_g], cntloc);
    }
}

// ================= K3: scan (block 0, self-cleans g_cnt) + graph_h ===========
__global__ void k_scan_graph(const int* __restrict__ timestep,
                             const float* __restrict__ Wt, const float* __restrict__ bt,
                             const float* __restrict__ Wc, const float* __restrict__ bc) {
    if (blockIdx.x == 0) {
        __shared__ int s[1024];
        const int t = threadIdx.x;
        int v0 = g_cnt[4*t], v1 = g_cnt[4*t+1], v2 = g_cnt[4*t+2], v3 = g_cnt[4*t+3];
        g_cnt[4*t] = 0; g_cnt[4*t+1] = 0; g_cnt[4*t+2] = 0; g_cnt[4*t+3] = 0;
        g_dinv[4*t]   = rsqrtf((float)(v0 + 1));
        g_dinv[4*t+1] = rsqrtf((float)(v1 + 1));
        g_dinv[4*t+2] = rsqrtf((float)(v2 + 1));
        g_dinv[4*t+3] = rsqrtf((float)(v3 + 1));
        int sum = v0 + v1 + v2 + v3;
        s[t] = sum; __syncthreads();
        for (int off = 1; off < 1024; off <<= 1) {
            int x = (t >= off) ? s[t - off] : 0;
            __syncthreads();
            s[t] += x;
            __syncthreads();
        }
        int excl = s[t] - sum;
        g_rowptr[4*t]   = excl;
        g_rowptr[4*t+1] = excl + v0;
        g_rowptr[4*t+2] = excl + v0 + v1;
        g_rowptr[4*t+3] = excl + v0 + v1 + v2;
        if (t == 1023) g_rowptr[NN] = excl + sum;
        return;
    }
    __shared__ float te[HH], pe[HH];
    const int g = blockIdx.x - 1, c = threadIdx.x;
    if (c < HH) {
        float tv = (float)timestep[g];
        const float L = 9.210340371976184f;
        if (c < 64) te[c] = cosf(tv * expf(-L * (float)c / 64.f));
        else        te[c] = sinf(tv * expf(-L * (float)(c - 64) / 64.f));
        float cntv = g_condcnt[g];
        pe[c] = g_condsum[g*HH + c] / fmaxf(cntv, 1.0f);
        g_condsum[g*HH + c] = 0.f;
    }
    __syncthreads();
    if (c == 0) g_condcnt[g] = 0.f;
    if (c < HH) {
        float a = bt[c] + bc[c];
        #pragma unroll 8
        for (int k = 0; k < HH; k++)
            a += te[k] * Wt[k*HH + c] + pe[k] * Wc[k*HH + c];
        g_gh[g*HH + c] = a;
    }
}

// ================= K4: CSR fill + gemm1 (32 rows/block, mask-split tf32) ======
#define SMEM1 ((HH*WSP + 32*WSP + 32*NDD + HH + 32) * 4)
__global__ void __launch_bounds__(512, 2)
k_fill_gemm1(const int* __restrict__ src, const int* __restrict__ dst,
             const float* __restrict__ W1,
             const float* __restrict__ x, const int* __restrict__ bmap,
             const float* __restrict__ Wn, const float* __restrict__ bn) {
    if (blockIdx.x < 64) {
        const int t = threadIdx.x;
        const int e0 = (blockIdx.x*512 + t) * 4;
        int4 s0 = *(const int4*)(src + e0);
        int4 d0 = *(const int4*)(dst + e0);
        g_csr[atomicAdd(&g_rowptr[d0.x], 1)] = s0.x;
        g_csr[atomicAdd(&g_rowptr[d0.y], 1)] = s0.y;
        g_csr[atomicAdd(&g_rowptr[d0.z], 1)] = s0.z;
        g_csr[atomicAdd(&g_rowptr[d0.w], 1)] = s0.w;
        return;
    }
    extern __shared__ float sm[];
    float* Ws  = sm;                        // 128 x 132 (k-major, padded)
    float* As  = sm + HH*WSP;               // 32 x 132
    float* xr  = As + 32*WSP;               // 32 x 16
    float* bns = xr + 32*NDD;               // 128
    int*   gidx = (int*)(bns + HH);         // 32

    const int blk = blockIdx.x - 64;
    const int i0 = blk * 32;
    const int t = threadIdx.x;
    const int lane = t & 31, w = t >> 5;    // warp 0..15

    // stage W1 (16 warps x 8 rows, 1 float4/lane)
    #pragma unroll
    for (int kt = 0; kt < 8; kt++) {
        int k = kt*16 + w;
        float4 v = ((const float4*)(W1 + k*HH))[lane];
        *(float4*)(Ws + k*WSP + lane*4) = v;
    }
    if (t < 128) bns[t] = bn[t];
    if (t < 32) gidx[t] = bmap[i0 + t];
    xr[t] = x[i0*NDD + t];                  // 512 = 32*16
    __syncthreads();

    // node embedding into As (512 threads -> 8 rows each at col c)
    {
        const int c = t & 127, rg = t >> 7;     // rg 0..3
        float wnk[NDD];
        #pragma unroll
        for (int k = 0; k < NDD; k++) wnk[k] = Wn[k*HH + c];
        #pragma unroll
        for (int r8 = 0; r8 < 8; r8++) {
            int r = rg*8 + r8;
            float a = bns[c] + g_gh[gidx[r]*HH + c];
            #pragma unroll
            for (int k = 0; k < NDD; k++) a += xr[r*NDD + k] * wnk[k];
            As[r*WSP + c] = a;
        }
    }
    __syncthreads();

    // mask-split tf32 mma: warp w -> rows rgb*16..+15, cols n0..n0+15
    const int g = lane >> 2, tig = lane & 3;
    const int rgb = w >> 3, wn = w & 7;
    const int n0 = wn * 16;
    float c0[4] = {0,0,0,0}, c1[4] = {0,0,0,0};
    const float* A0 = As + (rgb*16 + g)*WSP;
    const float* A1 = As + (rgb*16 + 8 + g)*WSP;
    #pragma unroll
    for (int kt = 0; kt < 16; kt++) {
        int k0 = kt*8;
        float av0 = A0[k0+tig],   av1 = A1[k0+tig];
        float av2 = A0[k0+tig+4], av3 = A1[k0+tig+4];
        unsigned ah0 = hi_of(av0), ah1 = hi_of(av1), ah2 = hi_of(av2), ah3 = hi_of(av3);
        unsigned al0 = lo_of(av0,ah0), al1 = lo_of(av1,ah1);
        unsigned al2 = lo_of(av2,ah2), al3 = lo_of(av3,ah3);
        const float* B0 = Ws + (k0+tig)*WSP;
        const float* B1 = Ws + (k0+tig+4)*WSP;
        float bv0 = B0[n0+g], bv1 = B1[n0+g], bv2 = B0[n0+8+g], bv3 = B1[n0+8+g];
        unsigned bh0 = hi_of(bv0), bh1 = hi_of(bv1), bh2 = hi_of(bv2), bh3 = hi_of(bv3);
        unsigned bl0 = lo_of(bv0,bh0), bl1 = lo_of(bv1,bh1);
        unsigned bl2 = lo_of(bv2,bh2), bl3 = lo_of(bv3,bh3);
        mma_tf32(c0, ah0,ah1,ah2,ah3, bh0,bh1);
        mma_tf32(c0, ah0,ah1,ah2,ah3, bl0,bl1);
        mma_tf32(c0, al0,al1,al2,al3, bh0,bh1);
        mma_tf32(c1, ah0,ah1,ah2,ah3, bh2,bh3);
        mma_tf32(c1, ah0,ah1,ah2,ah3, bl2,bl3);
        mma_tf32(c1, al0,al1,al2,al3, bh2,bh3);
    }
    const int r0 = i0 + rgb*16 + g, r1 = r0 + 8;
    const float d0 = g_dinv[r0], d1 = g_dinv[r1];
    *(float2*)&g_buf[0][r0*HH + n0 + 2*tig]     = make_float2(d0*c0[0], d0*c0[1]);
    *(float2*)&g_buf[0][r0*HH + n0 + 8 + 2*tig] = make_float2(d0*c1[0], d0*c1[1]);
    *(float2*)&g_buf[0][r1*HH + n0 + 2*tig]     = make_float2(d1*c0[2], d1*c0[3]);
    *(float2*)&g_buf[0][r1*HH + n0 + 8 + 2*tig] = make_float2(d1*c1[2], d1*c1[3]);
}

// ================= K5: agg1 + gemm2 fused (32 nodes/block, 1024 thr) =========
#define SMEM2 ((HH*WSP + 32*WSP) * 4)
__global__ void __launch_bounds__(1024, 1)
k_agg_gemm2(const float* __restrict__ b1, const float* __restrict__ W2) {
    extern __shared__ float sm[];
    float* Ws = sm;                 // 128 x 132
    float* As = sm + HH*WSP;        // 32 x 132
    const int t = threadIdx.x;
    const int lane = t & 31, w = t >> 5;   // warp 0..31

    // stage W2 (32 warps x 4 rows)
    #pragma unroll
    for (int kt = 0; kt < 4; kt++) {
        int k = kt*32 + w;
        float4 v = ((const float4*)(W2 + k*HH))[lane];
        *(float4*)(Ws + k*WSP + lane*4) = v;
    }

    // phase 1: warp-per-node aggregate (32 nodes)
    const int i = blockIdx.x*32 + w;
    const float4* __restrict__ xw = (const float4*)g_buf[0];
    float4 acc = xw[i*32 + lane];
    const int s0 = (i == 0) ? 0 : g_rowptr[i-1];
    const int s1 = g_rowptr[i];
    int e = s0;
    for (; e + 4 <= s1; e += 4) {
        int a0 = g_csr[e], a1 = g_csr[e+1], a2 = g_csr[e+2], a3 = g_csr[e+3];
        float4 v0 = xw[a0*32 + lane], v1 = xw[a1*32 + lane];
        float4 v2 = xw[a2*32 + lane], v3 = xw[a3*32 + lane];
        acc.x += (v0.x + v1.x) + (v2.x + v3.x);
        acc.y += (v0.y + v1.y) + (v2.y + v3.y);
        acc.z += (v0.z + v1.z) + (v2.z + v3.z);
        acc.w += (v0.w + v1.w) + (v2.w + v3.w);
    }
    for (; e < s1; e++) {
        float4 v = xw[g_csr[e]*32 + lane];
        acc.x += v.x; acc.y += v.y; acc.z += v.z; acc.w += v.w;
    }
    {
        const float di = g_dinv[i];
        const float4 b4 = ((const float4*)b1)[lane];
        float4 h;
        h.x = fmaxf(di*acc.x + b4.x, 0.f);
        h.y = fmaxf(di*acc.y + b4.y, 0.f);
        h.z = fmaxf(di*acc.z + b4.z, 0.f);
        h.w = fmaxf(di*acc.w + b4.w, 0.f);
        ((float4*)(As + w*WSP))[lane] = h;
    }
    __syncthreads();

    // phase 2: warp -> m16 n8 tile (rgb = w>>4 rows, n0 = (w&15)*8)
    const int g = lane >> 2, tig = lane & 3;
    const int rgb = w >> 4, wn = w & 15;
    const int n0 = wn * 8;
    float c0[4] = {0,0,0,0};
    const float* A0 = As + (rgb*16 + g)*WSP;
    const float* A1 = As + (rgb*16 + 8 + g)*WSP;
    #pragma unroll
    for (int kt = 0; kt < 16; kt++) {
        int k0 = kt*8;
        float av0 = A0[k0+tig],   av1 = A1[k0+tig];
        float av2 = A0[k0+tig+4], av3 = A1[k0+tig+4];
        unsigned ah0 = hi_of(av0), ah1 = hi_of(av1), ah2 = hi_of(av2), ah3 = hi_of(av3);
        unsigned al0 = lo_of(av0,ah0), al1 = lo_of(av1,ah1);
        unsigned al2 = lo_of(av2,ah2), al3 = lo_of(av3,ah3);
        const float* B0 = Ws + (k0+tig)*WSP;
        const float* B1 = Ws + (k0+tig+4)*WSP;
        float bv0 = B0[n0+g], bv1 = B1[n0+g];
        unsigned bh0 = hi_of(bv0), bh1 = hi_of(bv1);
        unsigned bl0 = lo_of(bv0,bh0), bl1 = lo_of(bv1,bh1);
        mma_tf32(c0, ah0,ah1,ah2,ah3, bh0,bh1);
        mma_tf32(c0, ah0,ah1,ah2,ah3, bl0,bl1);
        mma_tf32(c0, al0,al1,al2,al3, bh0,bh1);
    }
    const int i0 = blockIdx.x*32;
    const int r0 = i0 + rgb*16 + g, r1 = r0 + 8;
    const float d0 = g_dinv[r0], d1 = g_dinv[r1];
    *(float2*)&g_buf[1][r0*HH + n0 + 2*tig] = make_float2(d0*c0[0], d0*c0[1]);
    *(float2*)&g_buf[1][r1*HH + n0 + 2*tig] = make_float2(d1*c0[2], d1*c0[3]);
}

// ================= K6: agg2 + head fused (warp-per-node) =================
__global__ void k_agg_head(const float* __restrict__ bias,
                           const float* __restrict__ Wo, const float* __restrict__ bo,
                           const float* __restrict__ we, float* __restrict__ out_nodes) {
    const int i = (blockIdx.x * blockDim.x + threadIdx.x) >> 5;
    if (i >= NN) return;
    const int lane = threadIdx.x & 31;
    const float4* __restrict__ xw = (const float4*)g_buf[1];
    float4 acc = xw[i*32 + lane];
    const int s0 = (i == 0) ? 0 : g_rowptr[i-1];
    const int s1 = g_rowptr[i];
    int e = s0;
    for (; e + 4 <= s1; e += 4) {
        int a0 = g_csr[e], a1 = g_csr[e+1], a2 = g_csr[e+2], a3 = g_csr[e+3];
        float4 v0 = xw[a0*32 + lane], v1 = xw[a1*32 + lane];
        float4 v2 = xw[a2*32 + lane], v3 = xw[a3*32 + lane];
        acc.x += (v0.x + v1.x) + (v2.x + v3.x);
        acc.y += (v0.y + v1.y) + (v2.y + v3.y);
        acc.z += (v0.z + v1.z) + (v2.z + v3.z);
        acc.w += (v0.w + v1.w) + (v2.w + v3.w);
    }
    for (; e < s1; e++) {
        float4 v = xw[g_csr[e]*32 + lane];
        acc.x += v.x; acc.y += v.y; acc.z += v.z; acc.w += v.w;
    }
    const float di = g_dinv[i];
    const float4 b4 = ((const float4*)bias)[lane];
    float4 h;
    h.x = fmaxf(di*acc.x + b4.x, 0.f);
    h.y = fmaxf(di*acc.y + b4.y, 0.f);
    h.z = fmaxf(di*acc.z + b4.z, 0.f);
    h.w = fmaxf(di*acc.w + b4.w, 0.f);

    const float4 wl4 = ((const float4*)we)[lane];
    const float4 wr4 = ((const float4*)we)[32 + lane];
    float pl = h.x*wl4.x + h.y*wl4.y + h.z*wl4.z + h.w*wl4.w;
    float pr = h.x*wr4.x + h.y*wr4.y + h.z*wr4.z + h.w*wr4.w;

    float p[NDD];
    #pragma unroll
    for (int c = 0; c < NDD; c++) p[c] = 0.f;
    const float4* Wo4 = (const float4*)Wo;
    float hv[4] = {h.x, h.y, h.z, h.w};
    #pragma unroll
    for (int j = 0; j < 4; j++) {
        int k = lane*4 + j;
        #pragma unroll
        for (int c4 = 0; c4 < 4; c4++) {
            float4 wv = Wo4[k*4 + c4];
            p[c4*4+0] += hv[j]*wv.x; p[c4*4+1] += hv[j]*wv.y;
            p[c4*4+2] += hv[j]*wv.z; p[c4*4+3] += hv[j]*wv.w;
        }
    }
    #pragma unroll
    for (int off = 16; off > 0; off >>= 1) {
        pl += __shfl_down_sync(0xffffffffu, pl, off);
        pr += __shfl_down_sync(0xffffffffu, pr, off);
        #pragma unroll
        for (int c = 0; c < NDD; c++)
            p[c] += __shfl_down_sync(0xffffffffu, p[c], off);
    }
    if (lane == 0) {
        g_sl[i] = pl;
        g_sr[i] = pr;
        float4* on4 = (float4*)(out_nodes + i*NDD);
        const float4* bo4 = (const float4*)bo;
        #pragma unroll
        for (int c4 = 0; c4 < 4; c4++) {
            float4 b = bo4[c4];
            float4 v;
            v.x = p[c4*4+0] + b.x; v.y = p[c4*4+1] + b.y;
            v.z = p[c4*4+2] + b.z; v.w = p[c4*4+3] + b.w;
            on4[c4] = v;
        }
    }
}

// ================= K7: edges (row-pair balanced, float4 stores) ===============
__global__ void k_edges(const float* __restrict__ bedge, float* __restrict__ out_edges) {
    const float be = bedge[0];
    const int bi = blockIdx.x;
    const int t = threadIdx.x;
    #pragma unroll
    for (int half = 0; half < 2; half++) {
        const int i = (half == 0) ? bi : (NN - 2 - bi);
        if (half == 1 && i <= bi) break;
        const int cnt = NN - 1 - i;
        const long long off = (long long)i * (2LL*NN - i - 1) / 2;
        const float sl = g_sl[i] + be;
        float* o = out_edges + off;
        const float* sr = g_sr + i + 1;
        const int pre0 = (int)((4 - (off & 3)) & 3);
        const int pre = pre0 < cnt ? pre0 : cnt;
        if (t < pre) o[t] = sl + sr[t];
        const int nv = (cnt - pre) >> 2;
        float4* o4 = (float4*)(o + pre);
        for (int v = t; v < nv; v += 256) {
            int j = pre + v*4;
            float4 r;
            r.x = sl + sr[j];   r.y = sl + sr[j+1];
            r.z = sl + sr[j+2]; r.w = sl + sr[j+3];
            o4[v] = r;
        }
        const int tail0 = pre + nv*4;
        const int rem = cnt - tail0;
        if (t < rem) o[tail0 + t] = sl + sr[tail0 + t];
    }
}

// ================= launch =================
extern "C" void kernel_launch(void* const* d_in, const int* in_sizes, int n_in,
                              void* d_out, int out_size) {
    const float* x        = (const float*)d_in[0];
    const int*   eidx     = (const int*)d_in[1];
    const int*   timestep = (const int*)d_in[2];
    const int*   bmap     = (const int*)d_in[3];
    const int*   nuc      = (const int*)d_in[4];
    const void*  central  = d_in[5];
    const void*  backbone = d_in[6];
    const float* obj_x    = (const float*)d_in[7];
    const float* obj_pos  = (const float*)d_in[8];
    const int*   obatch   = (const int*)d_in[9];
    const float* Wn = (const float*)d_in[10]; const float* bn = (const float*)d_in[11];
    const float* Wc = (const float*)d_in[12]; const float* bc = (const float*)d_in[13];
    const float* Wt = (const float*)d_in[14]; const float* bt = (const float*)d_in[15];
    const float* W1 = (const float*)d_in[16]; const float* b1 = (const float*)d_in[17];
    const float* W2 = (const float*)d_in[18]; const float* b2 = (const float*)d_in[19];
    const float* Wo = (const float*)d_in[20]; const float* bo = (const float*)d_in[21];
    const float* we = (const float*)d_in[22]; const float* be = (const float*)d_in[23];

    float* out = (float*)d_out;
    float* out_nodes = out;
    float* out_edges = out + NN*NDD;

    const int* esrc = eidx;
    const int* edst = eidx + EE;

    cudaFuncSetAttribute(k_fill_gemm1, cudaFuncAttributeMaxDynamicSharedMemorySize, SMEM1);
    cudaFuncSetAttribute(k_agg_gemm2,  cudaFuncAttributeMaxDynamicSharedMemorySize, SMEM2);

    k_prep<<<32, 256>>>((const unsigned char*)central, (const unsigned char*)backbone);
    k_hist_cond<<<384, 256>>>(edst, obj_x, obj_pos, nuc, central, backbone, obatch, Wn, bn);
    k_scan_graph<<<9, 1024>>>(timestep, Wt, bt, Wc, bc);
    k_fill_gemm1<<<64 + NN/32, 512, SMEM1>>>(esrc, edst, W1, x, bmap, Wn, bn);
    k_agg_gemm2<<<NN/32, 1024, SMEM2>>>(b1, W2);
    k_agg_head<<<NN/8, 256>>>(b2, Wo, bo, we, out_nodes);
    k_edges<<<NN/2, 256>>>(be, out_edges);
}